// round 1
// baseline (speedup 1.0000x reference)
#include <cuda_runtime.h>

#define NE 8
#define NT 4096
#define DH 2048
#define DI 5632
#define NR 128

// ---------------- scratch (device globals; no allocation allowed) ----------
__device__ int   g_counts[NE];
__device__ int   g_offsets[NE + 1];
__device__ int   g_cursor[NE];
__device__ int   g_perm[NT];

__device__ float g_Agt[NE * DH * NR];   // (C_g @ A_g)^T per expert: [e][d][s]
__device__ float g_Aut[NE * DH * NR];   // (C_u @ A_u)^T
__device__ float g_Adt[NE * DI * NR];   // (C_d @ A_d)^T
__device__ float g_Bgt[NE * DI * NR];   // gate_B transposed: [e][r][di]
__device__ float g_But[NE * DI * NR];   // up_B transposed
__device__ float g_Bdt[NE * DH * NR];   // down_B transposed: [e][r][dh]

__device__ float g_Hg[NT * NR];         // permuted-order intermediates
__device__ float g_Hu[NT * NR];
__device__ float g_Hd[NT * NR];
__device__ float g_Y [NT * DI];         // permuted-order SwiGLU output

// ---------------- token->expert permutation ---------------------------------
__global__ void k_init() {
    int i = threadIdx.x;
    if (i < NE) { g_counts[i] = 0; g_cursor[i] = 0; }
}
__global__ void k_hist(const int* __restrict__ idx) {
    int t = blockIdx.x * 256 + threadIdx.x;
    if (t < NT) atomicAdd(&g_counts[idx[t]], 1);
}
__global__ void k_scan() {
    if (threadIdx.x == 0) {
        int s = 0;
        for (int e = 0; e < NE; ++e) { g_offsets[e] = s; s += g_counts[e]; }
        g_offsets[NE] = s;
    }
}
__global__ void k_scatter(const int* __restrict__ idx) {
    int t = blockIdx.x * 256 + threadIdx.x;
    if (t < NT) {
        int e = idx[t];
        int p = atomicAdd(&g_cursor[e], 1);
        g_perm[g_offsets[e] + p] = t;
    }
}

// ---------------- precompute: Out[e][d][s] = sum_r C[s][r] * A[e][r][d] -----
// grid: (DIN/32, R/64, E); block 256
template<int DIN>
__global__ void __launch_bounds__(256) fuse_CA_T(
    const float* __restrict__ A, const float* __restrict__ C,
    float* __restrict__ Out)
{
    __shared__ float As[NR][32];    // [r][dd]  16 KB
    __shared__ float Cs[64][NR];    // [ss][r]  32 KB
    int e = blockIdx.z;
    int sbase = blockIdx.y * 64;
    int dbase = blockIdx.x * 32;
    int tid = threadIdx.x;

    const float* Ae = A + (size_t)e * NR * DIN;
    #pragma unroll
    for (int l = 0; l < 16; ++l) {                  // 128 x 32
        int flat = tid + l * 256;
        int r = flat >> 5, dd = flat & 31;
        As[r][dd] = Ae[(size_t)r * DIN + dbase + dd];
    }
    #pragma unroll
    for (int l = 0; l < 32; ++l) {                  // 64 x 128
        int flat = tid + l * 256;
        int ss = flat >> 7, r = flat & 127;
        Cs[ss][r] = C[(sbase + ss) * NR + r];
    }
    __syncthreads();

    int dd  = tid & 31;
    int ss0 = (tid >> 5) * 8;
    float acc[8];
    #pragma unroll
    for (int j = 0; j < 8; ++j) acc[j] = 0.f;
    for (int r = 0; r < NR; ++r) {
        float a = As[r][dd];
        #pragma unroll
        for (int j = 0; j < 8; ++j) acc[j] += Cs[ss0 + j][r] * a;
    }
    float* O = Out + (size_t)e * DIN * NR + (size_t)(dbase + dd) * NR + sbase + ss0;
    #pragma unroll
    for (int j = 0; j < 8; ++j) O[j] = acc[j];
}

// ---------------- precompute: Bt[e][k][n] = B[e][n][k] ----------------------
// grid: (N/32, R/32, E); block (32, 8)
template<int N>
__global__ void transpose_B(const float* __restrict__ B, float* __restrict__ Bt)
{
    __shared__ float ts[32][33];
    int e  = blockIdx.z;
    int n0 = blockIdx.x * 32;
    int k0 = blockIdx.y * 32;
    int tx = threadIdx.x, ty = threadIdx.y;
    const float* Be = B + (size_t)e * N * NR;
    #pragma unroll
    for (int l = 0; l < 4; ++l) {
        int n = n0 + ty + l * 8;
        ts[ty + l * 8][tx] = Be[(size_t)n * NR + k0 + tx];
    }
    __syncthreads();
    float* Bte = Bt + (size_t)e * NR * N;
    #pragma unroll
    for (int l = 0; l < 4; ++l) {
        int k = k0 + ty + l * 8;
        Bte[(size_t)k * N + n0 + tx] = ts[tx][ty + l * 8];
    }
}

// ---------------- K1: Hg/Hu[i][r] = sum_d x[perm[i]][d] * A't[e][d][r] -------
// grid: (ceil(T/32)=128, E); block 256; tile 32 tokens x 128 r, BK=32
__global__ void __launch_bounds__(256) gemm_xA2(
    const float* __restrict__ X,
    const float* __restrict__ Wg, const float* __restrict__ Wu)
{
    __shared__ float Xs[32][33];
    __shared__ float Wsg[32][128];
    __shared__ float Wsu[32][128];
    __shared__ int rows[32];

    int e = blockIdx.y;
    int base = g_offsets[e], iend = g_offsets[e + 1];
    int i0 = base + blockIdx.x * 32;
    if (i0 >= iend) return;
    int tid = threadIdx.x;
    if (tid < 32) {
        int i = i0 + tid;
        rows[tid] = g_perm[i < iend ? i : i0];
    }
    __syncthreads();

    const float* Weg = Wg + (size_t)e * DH * NR;
    const float* Weu = Wu + (size_t)e * DH * NR;

    float ag[4][4] = {}, au[4][4] = {};
    int tx = tid & 31, ty = tid >> 5;
    int m0 = ty * 4, r0 = tx * 4;

    for (int kb = 0; kb < DH; kb += 32) {
        #pragma unroll
        for (int l = 0; l < 4; ++l) {
            int flat = tid + l * 256;
            int m = flat >> 5, k = flat & 31;
            Xs[m][k] = X[(size_t)rows[m] * DH + kb + k];
        }
        #pragma unroll
        for (int l = 0; l < 16; ++l) {
            int flat = tid + l * 256;
            int k = flat >> 7, r = flat & 127;
            Wsg[k][r] = Weg[(size_t)(kb + k) * NR + r];
            Wsu[k][r] = Weu[(size_t)(kb + k) * NR + r];
        }
        __syncthreads();
        #pragma unroll
        for (int k = 0; k < 32; ++k) {
            float4 wg = *(const float4*)&Wsg[k][r0];
            float4 wu = *(const float4*)&Wsu[k][r0];
            #pragma unroll
            for (int mi = 0; mi < 4; ++mi) {
                float xv = Xs[m0 + mi][k];
                ag[mi][0] += xv * wg.x; ag[mi][1] += xv * wg.y;
                ag[mi][2] += xv * wg.z; ag[mi][3] += xv * wg.w;
                au[mi][0] += xv * wu.x; au[mi][1] += xv * wu.y;
                au[mi][2] += xv * wu.z; au[mi][3] += xv * wu.w;
            }
        }
        __syncthreads();
    }
    #pragma unroll
    for (int mi = 0; mi < 4; ++mi) {
        int i = i0 + m0 + mi;
        if (i < iend) {
            *(float4*)&g_Hg[(size_t)i * NR + r0] =
                make_float4(ag[mi][0], ag[mi][1], ag[mi][2], ag[mi][3]);
            *(float4*)&g_Hu[(size_t)i * NR + r0] =
                make_float4(au[mi][0], au[mi][1], au[mi][2], au[mi][3]);
        }
    }
}

// ---------------- K2: Y[i][n] = silu(Hg . Bg[:,n]) * (Hu . Bu[:,n]) ----------
// grid: (DI/128=44, 128, E); block 256; K = 128
__global__ void __launch_bounds__(256) gemm_gateup(
    const float* __restrict__ Bgt, const float* __restrict__ But)
{
    __shared__ float Gs[32][33];
    __shared__ float Us[32][33];
    __shared__ float Wsg[32][128];
    __shared__ float Wsu[32][128];

    int e = blockIdx.z;
    int base = g_offsets[e], iend = g_offsets[e + 1];
    int i0 = base + blockIdx.y * 32;
    if (i0 >= iend) return;
    int nb = blockIdx.x * 128;
    int tid = threadIdx.x;

    const float* Bg = Bgt + (size_t)e * NR * DI;
    const float* Bu = But + (size_t)e * NR * DI;

    float ag[4][4] = {}, au[4][4] = {};
    int tx = tid & 31, ty = tid >> 5;
    int m0 = ty * 4, r0 = tx * 4;

    for (int kb = 0; kb < NR; kb += 32) {
        #pragma unroll
        for (int l = 0; l < 4; ++l) {
            int flat = tid + l * 256;
            int m = flat >> 5, k = flat & 31;
            int i = i0 + m; if (i >= iend) i = iend - 1;
            Gs[m][k] = g_Hg[(size_t)i * NR + kb + k];
            Us[m][k] = g_Hu[(size_t)i * NR + kb + k];
        }
        #pragma unroll
        for (int l = 0; l < 16; ++l) {
            int flat = tid + l * 256;
            int k = flat >> 7, r = flat & 127;
            Wsg[k][r] = Bg[(size_t)(kb + k) * DI + nb + r];
            Wsu[k][r] = Bu[(size_t)(kb + k) * DI + nb + r];
        }
        __syncthreads();
        #pragma unroll
        for (int k = 0; k < 32; ++k) {
            float4 wg = *(const float4*)&Wsg[k][r0];
            float4 wu = *(const float4*)&Wsu[k][r0];
            #pragma unroll
            for (int mi = 0; mi < 4; ++mi) {
                float gv = Gs[m0 + mi][k];
                float uv = Us[m0 + mi][k];
                ag[mi][0] += gv * wg.x; ag[mi][1] += gv * wg.y;
                ag[mi][2] += gv * wg.z; ag[mi][3] += gv * wg.w;
                au[mi][0] += uv * wu.x; au[mi][1] += uv * wu.y;
                au[mi][2] += uv * wu.z; au[mi][3] += uv * wu.w;
            }
        }
        __syncthreads();
    }
    #pragma unroll
    for (int mi = 0; mi < 4; ++mi) {
        int i = i0 + m0 + mi;
        if (i < iend) {
            float4 o; float g, u;
            g = ag[mi][0]; u = au[mi][0]; o.x = u * g / (1.f + __expf(-g));
            g = ag[mi][1]; u = au[mi][1]; o.y = u * g / (1.f + __expf(-g));
            g = ag[mi][2]; u = au[mi][2]; o.z = u * g / (1.f + __expf(-g));
            g = ag[mi][3]; u = au[mi][3]; o.w = u * g / (1.f + __expf(-g));
            *(float4*)&g_Y[(size_t)i * DI + nb + r0] = o;
        }
    }
}

// ---------------- K3: Hd[i][r] = sum_k Y[i][k] * Adt[e][k][r] ----------------
// grid: (128, E); block 256; K = DI
__global__ void __launch_bounds__(256) gemm_yAd(const float* __restrict__ Wt)
{
    __shared__ float Xs[32][33];
    __shared__ float Ws[32][128];

    int e = blockIdx.y;
    int base = g_offsets[e], iend = g_offsets[e + 1];
    int i0 = base + blockIdx.x * 32;
    if (i0 >= iend) return;
    int tid = threadIdx.x;

    const float* We = Wt + (size_t)e * DI * NR;

    float acc[4][4] = {};
    int tx = tid & 31, ty = tid >> 5;
    int m0 = ty * 4, r0 = tx * 4;

    for (int kb = 0; kb < DI; kb += 32) {
        #pragma unroll
        for (int l = 0; l < 4; ++l) {
            int flat = tid + l * 256;
            int m = flat >> 5, k = flat & 31;
            int i = i0 + m; if (i >= iend) i = iend - 1;
            Xs[m][k] = g_Y[(size_t)i * DI + kb + k];
        }
        #pragma unroll
        for (int l = 0; l < 16; ++l) {
            int flat = tid + l * 256;
            int k = flat >> 7, r = flat & 127;
            Ws[k][r] = We[(size_t)(kb + k) * NR + r];
        }
        __syncthreads();
        #pragma unroll
        for (int k = 0; k < 32; ++k) {
            float4 w = *(const float4*)&Ws[k][r0];
            #pragma unroll
            for (int mi = 0; mi < 4; ++mi) {
                float xv = Xs[m0 + mi][k];
                acc[mi][0] += xv * w.x; acc[mi][1] += xv * w.y;
                acc[mi][2] += xv * w.z; acc[mi][3] += xv * w.w;
            }
        }
        __syncthreads();
    }
    #pragma unroll
    for (int mi = 0; mi < 4; ++mi) {
        int i = i0 + m0 + mi;
        if (i < iend) {
            *(float4*)&g_Hd[(size_t)i * NR + r0] =
                make_float4(acc[mi][0], acc[mi][1], acc[mi][2], acc[mi][3]);
        }
    }
}

// ---------------- K4: out[perm[i]][n] = Hd[i] . Bd[:,n] + bias[e][n] ---------
// grid: (DH/128=16, 128, E); block 256; K = 128
__global__ void __launch_bounds__(256) gemm_down(
    const float* __restrict__ Bdt, const float* __restrict__ bias,
    float* __restrict__ out)
{
    __shared__ float Xs[32][33];
    __shared__ float Ws[32][128];
    __shared__ int rows[32];

    int e = blockIdx.z;
    int base = g_offsets[e], iend = g_offsets[e + 1];
    int i0 = base + blockIdx.y * 32;
    if (i0 >= iend) return;
    int nb = blockIdx.x * 128;
    int tid = threadIdx.x;
    if (tid < 32) {
        int i = i0 + tid;
        rows[tid] = g_perm[i < iend ? i : i0];
    }
    __syncthreads();

    const float* Bd = Bdt + (size_t)e * NR * DH;

    float acc[4][4] = {};
    int tx = tid & 31, ty = tid >> 5;
    int m0 = ty * 4, r0 = tx * 4;

    for (int kb = 0; kb < NR; kb += 32) {
        #pragma unroll
        for (int l = 0; l < 4; ++l) {
            int flat = tid + l * 256;
            int m = flat >> 5, k = flat & 31;
            int i = i0 + m; if (i >= iend) i = iend - 1;
            Xs[m][k] = g_Hd[(size_t)i * NR + kb + k];
        }
        #pragma unroll
        for (int l = 0; l < 16; ++l) {
            int flat = tid + l * 256;
            int k = flat >> 7, r = flat & 127;
            Ws[k][r] = Bd[(size_t)(kb + k) * DH + nb + r];
        }
        __syncthreads();
        #pragma unroll
        for (int k = 0; k < 32; ++k) {
            float4 w = *(const float4*)&Ws[k][r0];
            #pragma unroll
            for (int mi = 0; mi < 4; ++mi) {
                float xv = Xs[m0 + mi][k];
                acc[mi][0] += xv * w.x; acc[mi][1] += xv * w.y;
                acc[mi][2] += xv * w.z; acc[mi][3] += xv * w.w;
            }
        }
        __syncthreads();
    }

    float4 b4 = *(const float4*)&bias[(size_t)e * DH + nb + r0];
    #pragma unroll
    for (int mi = 0; mi < 4; ++mi) {
        int i = i0 + m0 + mi;
        if (i < iend) {
            float4 o = make_float4(acc[mi][0] + b4.x, acc[mi][1] + b4.y,
                                   acc[mi][2] + b4.z, acc[mi][3] + b4.w);
            *(float4*)&out[(size_t)rows[m0 + mi] * DH + nb + r0] = o;
        }
    }
}

// ---------------- launch -----------------------------------------------------
extern "C" void kernel_launch(void* const* d_in, const int* in_sizes, int n_in,
                              void* d_out, int out_size)
{
    const float* x         = (const float*)d_in[0];
    const int*   eidx      = (const int*)  d_in[1];
    const float* gate_A    = (const float*)d_in[2];
    const float* gate_C    = (const float*)d_in[3];
    const float* gate_B    = (const float*)d_in[4];
    const float* up_A      = (const float*)d_in[5];
    const float* up_C      = (const float*)d_in[6];
    const float* up_B      = (const float*)d_in[7];
    const float* down_A    = (const float*)d_in[8];
    const float* down_C    = (const float*)d_in[9];
    const float* down_B    = (const float*)d_in[10];
    const float* down_bias = (const float*)d_in[11];
    float* out = (float*)d_out;

    float *pAgt, *pAut, *pAdt, *pBgt, *pBut, *pBdt;
    cudaGetSymbolAddress((void**)&pAgt, g_Agt);
    cudaGetSymbolAddress((void**)&pAut, g_Aut);
    cudaGetSymbolAddress((void**)&pAdt, g_Adt);
    cudaGetSymbolAddress((void**)&pBgt, g_Bgt);
    cudaGetSymbolAddress((void**)&pBut, g_But);
    cudaGetSymbolAddress((void**)&pBdt, g_Bdt);

    // permutation
    k_init<<<1, 32>>>();
    k_hist<<<NT / 256, 256>>>(eidx);
    k_scan<<<1, 1>>>();
    k_scatter<<<NT / 256, 256>>>(eidx);

    // weight precompute: fold C into A (transposed), transpose B
    fuse_CA_T<DH><<<dim3(DH / 32, 2, NE), 256>>>(gate_A, gate_C, pAgt);
    fuse_CA_T<DH><<<dim3(DH / 32, 2, NE), 256>>>(up_A,   up_C,   pAut);
    fuse_CA_T<DI><<<dim3(DI / 32, 2, NE), 256>>>(down_A, down_C, pAdt);
    transpose_B<DI><<<dim3(DI / 32, 4, NE), dim3(32, 8)>>>(gate_B, pBgt);
    transpose_B<DI><<<dim3(DI / 32, 4, NE), dim3(32, 8)>>>(up_B,   pBut);
    transpose_B<DH><<<dim3(DH / 32, 4, NE), dim3(32, 8)>>>(down_B, pBdt);

    // main pipeline
    gemm_xA2   <<<dim3(NT / 32, NE), 256>>>(x, pAgt, pAut);
    gemm_gateup<<<dim3(DI / 128, NT / 32, NE), 256>>>(pBgt, pBut);
    gemm_yAd   <<<dim3(NT / 32, NE), 256>>>(pAdt);
    gemm_down  <<<dim3(DH / 128, NT / 32, NE), 256>>>(pBdt, down_bias, out);
}

// round 2
// speedup vs baseline: 1.5889x; 1.5889x over previous
#include <cuda_runtime.h>

#define NE 8
#define NT 4096
#define DH 2048
#define DI 5632
#define NR 128

// ---------------- scratch (device globals; no allocation allowed) ----------
__device__ int   g_counts[NE];
__device__ int   g_offsets[NE + 1];
__device__ int   g_cursor[NE];
__device__ int   g_perm[NT];

__device__ float g_A1t[NE * DH * 256];   // (C@A)^T gate|up interleaved: [e][d][256]
__device__ float g_Adt[NE * DI * NR];    // (C_d @ A_d)^T: [e][di][r]
__device__ float g_Bgt[NE * NR * DI];    // gate_B^T: [e][r][di]
__device__ float g_But[NE * NR * DI];    // up_B^T
__device__ float g_Bdt[NE * NR * DH];    // down_B^T: [e][r][dh]

__device__ float g_H [NT * 256];         // K1 output: Hg cols 0..127, Hu cols 128..255
__device__ float g_G [NT * DI];          // gate pre-activation
__device__ float g_Y [NT * DI];          // swiglu output
__device__ float g_Hd[NT * NR];          // down low-rank intermediate
__device__ float g_P1[4 * NT * 256];     // split-K partials for K1
__device__ float g_P3[8 * NT * NR];      // split-K partials for K3

// ---------------- token->expert permutation ---------------------------------
__global__ void k_init() {
    int i = threadIdx.x;
    if (i < NE) { g_counts[i] = 0; g_cursor[i] = 0; }
}
__global__ void k_hist(const int* __restrict__ idx) {
    int t = blockIdx.x * 256 + threadIdx.x;
    if (t < NT) atomicAdd(&g_counts[idx[t]], 1);
}
__global__ void k_scan() {
    if (threadIdx.x == 0) {
        int s = 0;
        for (int e = 0; e < NE; ++e) { g_offsets[e] = s; s += g_counts[e]; }
        g_offsets[NE] = s;
    }
}
__global__ void k_scatter(const int* __restrict__ idx) {
    int t = blockIdx.x * 256 + threadIdx.x;
    if (t < NT) {
        int e = idx[t];
        int p = atomicAdd(&g_cursor[e], 1);
        g_perm[g_offsets[e] + p] = t;
    }
}

// ---------------- precompute: Out[e][d][ooff+s] = sum_r C[s][r]*A[e][r][d] --
// grid: (DIN/32, NR/64, E); block 256
template<int DIN>
__global__ void __launch_bounds__(256) fuse_CA_T(
    const float* __restrict__ A, const float* __restrict__ C,
    float* __restrict__ Out, int ostride, int ooff)
{
    __shared__ float As[NR][32];
    __shared__ float Cs[64][NR];
    int e = blockIdx.z;
    int sbase = blockIdx.y * 64;
    int dbase = blockIdx.x * 32;
    int tid = threadIdx.x;

    const float* Ae = A + (size_t)e * NR * DIN;
    #pragma unroll
    for (int l = 0; l < 16; ++l) {
        int flat = tid + l * 256;
        int r = flat >> 5, dd = flat & 31;
        As[r][dd] = Ae[(size_t)r * DIN + dbase + dd];
    }
    #pragma unroll
    for (int l = 0; l < 32; ++l) {
        int flat = tid + l * 256;
        int ss = flat >> 7, r = flat & 127;
        Cs[ss][r] = C[(sbase + ss) * NR + r];
    }
    __syncthreads();

    int dd  = tid & 31;
    int ss0 = (tid >> 5) * 8;
    float acc[8];
    #pragma unroll
    for (int j = 0; j < 8; ++j) acc[j] = 0.f;
    for (int r = 0; r < NR; ++r) {
        float a = As[r][dd];
        #pragma unroll
        for (int j = 0; j < 8; ++j) acc[j] += Cs[ss0 + j][r] * a;
    }
    float* O = Out + (size_t)e * DIN * ostride
                   + (size_t)(dbase + dd) * ostride + ooff + sbase + ss0;
    #pragma unroll
    for (int j = 0; j < 8; ++j) O[j] = acc[j];
}

// ---------------- precompute: Bt[e][k][n] = B[e][n][k] ----------------------
template<int N>
__global__ void transpose_B(const float* __restrict__ B, float* __restrict__ Bt)
{
    __shared__ float ts[32][33];
    int e  = blockIdx.z;
    int n0 = blockIdx.x * 32;
    int k0 = blockIdx.y * 32;
    int tx = threadIdx.x, ty = threadIdx.y;
    const float* Be = B + (size_t)e * N * NR;
    #pragma unroll
    for (int l = 0; l < 4; ++l) {
        int n = n0 + ty + l * 8;
        ts[ty + l * 8][tx] = Be[(size_t)n * NR + k0 + tx];
    }
    __syncthreads();
    float* Bte = Bt + (size_t)e * NR * N;
    #pragma unroll
    for (int l = 0; l < 4; ++l) {
        int k = k0 + ty + l * 8;
        Bte[(size_t)k * N + n0 + tx] = ts[tx][ty + l * 8];
    }
}

// ---------------- unified 128x128x16 double-buffered SGEMM ------------------
// EPI: 0 = plain store, 1 = swiglu (C = acc * silu(Gbuf)), 2 = bias + perm scatter
#define BM 128
#define BN 128
#define BKK 16
#define APAD 4

template<bool GATHER, int EPI, int SPLITK>
__global__ void __launch_bounds__(256, 2) sgemm_k(
    const float* __restrict__ A, int lda,
    const float* __restrict__ B, int ldb, size_t strideBe,
    int Ktot,
    float* __restrict__ C, int ldc, size_t splitStride,
    const float* __restrict__ Gbuf,
    const float* __restrict__ bias)
{
    __shared__ float As[2][BKK][BM + APAD];
    __shared__ float Bs[2][BKK][BN];
    __shared__ int rows[BM];

    int z = blockIdx.z;
    int e = z / SPLITK, sk = z % SPLITK;
    int base = g_offsets[e], iend = g_offsets[e + 1];
    int i0 = base + blockIdx.y * BM;
    if (i0 >= iend) return;
    int nb = blockIdx.x * BN;
    int tid = threadIdx.x;

    if (tid < BM) {
        int i = i0 + tid; if (i >= iend) i = iend - 1;
        rows[tid] = GATHER ? g_perm[i] : i;
    }
    __syncthreads();

    const float* Bp = B + (size_t)e * strideBe;
    C += (size_t)sk * splitStride;
    int kstep = Ktot / SPLITK;
    int kbeg = sk * kstep;
    int nk = kstep / BKK;

    int arow = tid >> 2;            // 0..63, +64
    int ac4  = (tid & 3) * 4;       // k offset 0,4,8,12
    int brow = tid >> 5;            // 0..7, +8
    int bcol = (tid & 31) * 4;      // 0..124

    // prologue: tile 0
    {
        #pragma unroll
        for (int l = 0; l < 2; ++l) {
            int r = arow + l * 64;
            float4 v = *(const float4*)&A[(size_t)rows[r] * lda + kbeg + ac4];
            As[0][ac4 + 0][r] = v.x; As[0][ac4 + 1][r] = v.y;
            As[0][ac4 + 2][r] = v.z; As[0][ac4 + 3][r] = v.w;
        }
        #pragma unroll
        for (int l = 0; l < 2; ++l) {
            int r = brow + l * 8;
            *(float4*)&Bs[0][r][bcol] =
                *(const float4*)&Bp[(size_t)(kbeg + r) * ldb + nb + bcol];
        }
    }
    __syncthreads();

    int m0 = (tid >> 4) * 8, n0 = (tid & 15) * 8;
    float acc[8][8] = {};
    float4 stA[2], stB[2];

    for (int t = 0; t < nk; ++t) {
        int buf = t & 1;
        if (t + 1 < nk) {
            int kb = kbeg + (t + 1) * BKK;
            #pragma unroll
            for (int l = 0; l < 2; ++l)
                stA[l] = *(const float4*)&A[(size_t)rows[arow + l * 64] * lda + kb + ac4];
            #pragma unroll
            for (int l = 0; l < 2; ++l)
                stB[l] = *(const float4*)&Bp[(size_t)(kb + brow + l * 8) * ldb + nb + bcol];
        }
        #pragma unroll
        for (int k = 0; k < BKK; ++k) {
            float4 a0 = *(const float4*)&As[buf][k][m0];
            float4 a1 = *(const float4*)&As[buf][k][m0 + 4];
            float4 b0 = *(const float4*)&Bs[buf][k][n0];
            float4 b1 = *(const float4*)&Bs[buf][k][n0 + 4];
            float am[8] = {a0.x, a0.y, a0.z, a0.w, a1.x, a1.y, a1.z, a1.w};
            float bn[8] = {b0.x, b0.y, b0.z, b0.w, b1.x, b1.y, b1.z, b1.w};
            #pragma unroll
            for (int ii = 0; ii < 8; ++ii)
                #pragma unroll
                for (int jj = 0; jj < 8; ++jj)
                    acc[ii][jj] += am[ii] * bn[jj];
        }
        if (t + 1 < nk) {
            int nbuf = buf ^ 1;
            #pragma unroll
            for (int l = 0; l < 2; ++l) {
                int r = arow + l * 64;
                As[nbuf][ac4 + 0][r] = stA[l].x; As[nbuf][ac4 + 1][r] = stA[l].y;
                As[nbuf][ac4 + 2][r] = stA[l].z; As[nbuf][ac4 + 3][r] = stA[l].w;
            }
            #pragma unroll
            for (int l = 0; l < 2; ++l)
                *(float4*)&Bs[nbuf][brow + l * 8][bcol] = stB[l];
        }
        __syncthreads();
    }

    // epilogue
    float4 bb0, bb1;
    if (EPI == 2) {
        bb0 = *(const float4*)&bias[(size_t)e * DH + nb + n0];
        bb1 = *(const float4*)&bias[(size_t)e * DH + nb + n0 + 4];
    }
    #pragma unroll
    for (int ii = 0; ii < 8; ++ii) {
        int gi = i0 + m0 + ii;
        if (gi >= iend) continue;
        size_t co = (size_t)gi * ldc + nb + n0;
        if (EPI == 0) {
            *(float4*)&C[co]     = make_float4(acc[ii][0], acc[ii][1], acc[ii][2], acc[ii][3]);
            *(float4*)&C[co + 4] = make_float4(acc[ii][4], acc[ii][5], acc[ii][6], acc[ii][7]);
        } else if (EPI == 1) {
            float o[8];
            #pragma unroll
            for (int jj = 0; jj < 8; ++jj) {
                float g = Gbuf[co + jj];
                o[jj] = acc[ii][jj] * g / (1.f + __expf(-g));
            }
            *(float4*)&C[co]     = make_float4(o[0], o[1], o[2], o[3]);
            *(float4*)&C[co + 4] = make_float4(o[4], o[5], o[6], o[7]);
        } else {
            int orow = g_perm[gi];
            size_t oo = (size_t)orow * ldc + nb + n0;
            *(float4*)&C[oo]     = make_float4(acc[ii][0] + bb0.x, acc[ii][1] + bb0.y,
                                               acc[ii][2] + bb0.z, acc[ii][3] + bb0.w);
            *(float4*)&C[oo + 4] = make_float4(acc[ii][4] + bb1.x, acc[ii][5] + bb1.y,
                                               acc[ii][6] + bb1.z, acc[ii][7] + bb1.w);
        }
    }
}

// ---------------- split-K reduction ------------------------------------------
template<int S>
__global__ void reduce_k(const float4* __restrict__ P, float4* __restrict__ O,
                         int n4, size_t stride4)
{
    int i = blockIdx.x * 256 + threadIdx.x;
    if (i >= n4) return;
    float4 s = P[i];
    #pragma unroll
    for (int k = 1; k < S; ++k) {
        float4 v = P[(size_t)k * stride4 + i];
        s.x += v.x; s.y += v.y; s.z += v.z; s.w += v.w;
    }
    O[i] = s;
}

// ---------------- launch -----------------------------------------------------
extern "C" void kernel_launch(void* const* d_in, const int* in_sizes, int n_in,
                              void* d_out, int out_size)
{
    const float* x         = (const float*)d_in[0];
    const int*   eidx      = (const int*)  d_in[1];
    const float* gate_A    = (const float*)d_in[2];
    const float* gate_C    = (const float*)d_in[3];
    const float* gate_B    = (const float*)d_in[4];
    const float* up_A      = (const float*)d_in[5];
    const float* up_C      = (const float*)d_in[6];
    const float* up_B      = (const float*)d_in[7];
    const float* down_A    = (const float*)d_in[8];
    const float* down_C    = (const float*)d_in[9];
    const float* down_B    = (const float*)d_in[10];
    const float* down_bias = (const float*)d_in[11];
    float* out = (float*)d_out;

    float *pA1t, *pAdt, *pBgt, *pBut, *pBdt, *pH, *pG, *pY, *pHd, *pP1, *pP3;
    cudaGetSymbolAddress((void**)&pA1t, g_A1t);
    cudaGetSymbolAddress((void**)&pAdt, g_Adt);
    cudaGetSymbolAddress((void**)&pBgt, g_Bgt);
    cudaGetSymbolAddress((void**)&pBut, g_But);
    cudaGetSymbolAddress((void**)&pBdt, g_Bdt);
    cudaGetSymbolAddress((void**)&pH,   g_H);
    cudaGetSymbolAddress((void**)&pG,   g_G);
    cudaGetSymbolAddress((void**)&pY,   g_Y);
    cudaGetSymbolAddress((void**)&pHd,  g_Hd);
    cudaGetSymbolAddress((void**)&pP1,  g_P1);
    cudaGetSymbolAddress((void**)&pP3,  g_P3);

    // permutation
    k_init<<<1, 32>>>();
    k_hist<<<NT / 256, 256>>>(eidx);
    k_scan<<<1, 1>>>();
    k_scatter<<<NT / 256, 256>>>(eidx);

    // weight precompute
    fuse_CA_T<DH><<<dim3(DH / 32, 2, NE), 256>>>(gate_A, gate_C, pA1t, 256, 0);
    fuse_CA_T<DH><<<dim3(DH / 32, 2, NE), 256>>>(up_A,   up_C,   pA1t, 256, 128);
    fuse_CA_T<DI><<<dim3(DI / 32, 2, NE), 256>>>(down_A, down_C, pAdt, 128, 0);
    transpose_B<DI><<<dim3(DI / 32, 4, NE), dim3(32, 8)>>>(gate_B, pBgt);
    transpose_B<DI><<<dim3(DI / 32, 4, NE), dim3(32, 8)>>>(up_B,   pBut);
    transpose_B<DH><<<dim3(DH / 32, 4, NE), dim3(32, 8)>>>(down_B, pBdt);

    // K1: H[T,256] = x_perm @ A1t   (split-K 4 -> partials -> reduce)
    sgemm_k<true, 0, 4><<<dim3(256 / BN, NT / BM, NE * 4), 256>>>(
        x, DH, pA1t, 256, (size_t)DH * 256, DH,
        pP1, 256, (size_t)NT * 256, nullptr, nullptr);
    reduce_k<4><<<(NT * 256 / 4 + 255) / 256, 256>>>(
        (const float4*)pP1, (float4*)pH, NT * 256 / 4, (size_t)NT * 256 / 4);

    // K2a: G[T,DI] = Hg @ Bgt
    sgemm_k<false, 0, 1><<<dim3(DI / BN, NT / BM, NE), 256>>>(
        pH, 256, pBgt, DI, (size_t)NR * DI, NR,
        pG, DI, 0, nullptr, nullptr);
    // K2b: Y[T,DI] = silu(G) * (Hu @ But)
    sgemm_k<false, 1, 1><<<dim3(DI / BN, NT / BM, NE), 256>>>(
        pH + 128, 256, pBut, DI, (size_t)NR * DI, NR,
        pY, DI, 0, pG, nullptr);

    // K3: Hd[T,128] = Y @ Adt   (split-K 8 -> partials -> reduce)
    sgemm_k<false, 0, 8><<<dim3(NR / BN, NT / BM, NE * 8), 256>>>(
        pY, DI, pAdt, NR, (size_t)DI * NR, DI,
        pP3, NR, (size_t)NT * NR, nullptr, nullptr);
    reduce_k<8><<<(NT * NR / 4 + 255) / 256, 256>>>(
        (const float4*)pP3, (float4*)pHd, NT * NR / 4, (size_t)NT * NR / 4);

    // K4: out[perm[i],:] = Hd @ Bdt + bias[e]
    sgemm_k<false, 2, 1><<<dim3(DH / BN, NT / BM, NE), 256>>>(
        pHd, NR, pBdt, DH, (size_t)NR * DH, NR,
        out, DH, 0, nullptr, down_bias);
}

// round 4
// speedup vs baseline: 2.5805x; 1.6240x over previous
#include <cuda_runtime.h>
#include <cstdint>

#define NE 8
#define NT 4096
#define DH 2048
#define DI 5632
#define NR 128

__device__ __forceinline__ float tf32r(float v) {
    uint32_t u;
    asm("cvt.rna.tf32.f32 %0, %1;" : "=r"(u) : "f"(v));
    return __uint_as_float(u);
}

__device__ __forceinline__ void mma_tf32(
    float c[4], const uint32_t a[4], const uint32_t b[2])
{
    asm volatile(
        "mma.sync.aligned.m16n8k8.row.col.f32.tf32.tf32.f32 "
        "{%0,%1,%2,%3}, {%4,%5,%6,%7}, {%8,%9}, {%0,%1,%2,%3};"
        : "+f"(c[0]), "+f"(c[1]), "+f"(c[2]), "+f"(c[3])
        : "r"(a[0]), "r"(a[1]), "r"(a[2]), "r"(a[3]),
          "r"(b[0]), "r"(b[1]));
}

// ===================== scratch globals ======================================
__device__ int   g_counts[NE];
__device__ int   g_offsets[NE + 1];
__device__ int   g_cursor[NE];
__device__ int   g_perm[NT];

__device__ float g_W1[NE * DH * 256];    // [e][d][s]: s 0..127 gate, 128..255 up (tf32)
__device__ float g_W3[NE * DI * NR];     // [e][di][r] (tf32)
__device__ float g_Bgt[NE * NR * DI];    // gate_B^T [e][r][di] (tf32)
__device__ float g_But[NE * NR * DI];    // up_B^T (tf32)
__device__ float g_Bdt[NE * NR * DH];    // down_B^T [e][r][dh] (tf32)

__device__ float g_H [NT * 256];
__device__ float g_G [NT * DI];
__device__ float g_Y [NT * DI];
__device__ float g_Hd[NT * NR];
__device__ float g_P1[4 * NT * 256];
__device__ float g_P3[8 * NT * NR];

// ===================== permutation ==========================================
__global__ void k_init() {
    int i = threadIdx.x;
    if (i < NE) { g_counts[i] = 0; g_cursor[i] = 0; }
}
__global__ void k_hist(const int* __restrict__ idx) {
    int t = blockIdx.x * 256 + threadIdx.x;
    if (t < NT) atomicAdd(&g_counts[idx[t]], 1);
}
__global__ void k_scan() {
    if (threadIdx.x == 0) {
        int s = 0;
        for (int e = 0; e < NE; ++e) { g_offsets[e] = s; s += g_counts[e]; }
        g_offsets[NE] = s;
    }
}
__global__ void k_scatter(const int* __restrict__ idx) {
    int t = blockIdx.x * 256 + threadIdx.x;
    if (t < NT) {
        int e = idx[t];
        int p = atomicAdd(&g_cursor[e], 1);
        g_perm[g_offsets[e] + p] = t;
    }
}

// ===================== fold C into A: Out[e][d][ooff+s] (tf32) ==============
template<int DIN>
__global__ void __launch_bounds__(256) fuse_CA_T(
    const float* __restrict__ A, const float* __restrict__ C,
    float* __restrict__ Out, int ostride, int ooff)
{
    __shared__ float As[NR][32];
    __shared__ float Cs[64][NR];
    int e = blockIdx.z;
    int sbase = blockIdx.y * 64;
    int dbase = blockIdx.x * 32;
    int tid = threadIdx.x;

    const float* Ae = A + (size_t)e * NR * DIN;
    #pragma unroll
    for (int l = 0; l < 16; ++l) {
        int flat = tid + l * 256;
        int r = flat >> 5, dd = flat & 31;
        As[r][dd] = Ae[(size_t)r * DIN + dbase + dd];
    }
    #pragma unroll
    for (int l = 0; l < 32; ++l) {
        int flat = tid + l * 256;
        int ss = flat >> 7, r = flat & 127;
        Cs[ss][r] = C[(sbase + ss) * NR + r];
    }
    __syncthreads();

    int dd  = tid & 31;
    int ss0 = (tid >> 5) * 8;
    float acc[8];
    #pragma unroll
    for (int j = 0; j < 8; ++j) acc[j] = 0.f;
    for (int r = 0; r < NR; ++r) {
        float a = As[r][dd];
        #pragma unroll
        for (int j = 0; j < 8; ++j) acc[j] += Cs[ss0 + j][r] * a;
    }
    float* O = Out + (size_t)e * DIN * ostride
                   + (size_t)(dbase + dd) * ostride + ooff + sbase + ss0;
    #pragma unroll
    for (int j = 0; j < 8; ++j) O[j] = tf32r(acc[j]);
}

// ===================== transpose B (tf32): Bt[e][k][n] = B[e][n][k] =========
template<int N>
__global__ void transpose_B(const float* __restrict__ B, float* __restrict__ Bt)
{
    __shared__ float ts[32][33];
    int e  = blockIdx.z;
    int n0 = blockIdx.x * 32;
    int k0 = blockIdx.y * 32;
    int tx = threadIdx.x, ty = threadIdx.y;
    const float* Be = B + (size_t)e * N * NR;
    #pragma unroll
    for (int l = 0; l < 4; ++l) {
        int n = n0 + ty + l * 8;
        ts[ty + l * 8][tx] = Be[(size_t)n * NR + k0 + tx];
    }
    __syncthreads();
    float* Bte = Bt + (size_t)e * NR * N;
    #pragma unroll
    for (int l = 0; l < 4; ++l) {
        int k = k0 + ty + l * 8;
        Bte[(size_t)k * N + n0 + tx] = tf32r(ts[tx][ty + l * 8]);
    }
}

// ===================== tf32 mma.sync GEMM ===================================
// D[i][n] = sum_k A[i][k] * B[k][nb+n]; 128x128 tile, BK=16, double-buffered.
// EPI 0: raw store. EPI 1: swiglu (C = acc * silu(Gbuf)). EPI 2: bias + scatter.
#define BM 128
#define BN 128
#define BK 16
#define SPITCH 140

template<bool GATHER, int EPI, int SPLITK>
__global__ void __launch_bounds__(256, 2) mma_gemm(
    const float* __restrict__ A, int lda,
    const float* __restrict__ Bglob, int ldb, size_t strideBe, int Ktot,
    float* __restrict__ C, int ldc, size_t splitStride,
    const float* __restrict__ Gbuf, const float* __restrict__ bias)
{
    __shared__ float As[2][BK][SPITCH];
    __shared__ float Bs[2][BK][SPITCH];
    __shared__ int rows[BM];

    int z = blockIdx.z;
    int e = z / SPLITK, sk = z % SPLITK;
    int base = g_offsets[e], iend = g_offsets[e + 1];
    int i0 = base + blockIdx.y * BM;
    if (i0 >= iend) return;
    int nb = blockIdx.x * BN;
    int tid = threadIdx.x;

    if (tid < BM) {
        int i = i0 + tid; if (i >= iend) i = iend - 1;
        rows[tid] = GATHER ? g_perm[i] : i;
    }
    __syncthreads();

    const float* Bp = Bglob + (size_t)e * strideBe;
    C += (size_t)sk * splitStride;
    int kstep = Ktot / SPLITK;
    int kbeg  = sk * kstep;
    int nk    = kstep / BK;

    int lane = tid & 31, wid = tid >> 5;
    int wm = wid >> 1, wn = wid & 1;       // 4 x 2 warps
    int gq = lane >> 2, tig = lane & 3;

    // staging indices
    int am  = tid >> 2;                    // 0..63 (+64)
    int af4 = (tid & 3) * 4;               // k offset
    int bk  = tid >> 5;                    // 0..7 (+8)
    int bn4 = (tid & 31) * 4;

    float acc[2][8][4];
    #pragma unroll
    for (int mt = 0; mt < 2; ++mt)
        #pragma unroll
        for (int nt = 0; nt < 8; ++nt)
            #pragma unroll
            for (int j = 0; j < 4; ++j) acc[mt][nt][j] = 0.f;

    // prologue: tile 0 -> buf 0
    #pragma unroll
    for (int l = 0; l < 2; ++l) {
        int m = am + l * 64;
        float4 v = *(const float4*)&A[(size_t)rows[m] * lda + kbeg + af4];
        As[0][af4 + 0][m] = tf32r(v.x); As[0][af4 + 1][m] = tf32r(v.y);
        As[0][af4 + 2][m] = tf32r(v.z); As[0][af4 + 3][m] = tf32r(v.w);
    }
    #pragma unroll
    for (int l = 0; l < 2; ++l) {
        int k = bk + l * 8;
        float4 v = *(const float4*)&Bp[(size_t)(kbeg + k) * ldb + nb + bn4];
        Bs[0][k][bn4 + 0] = tf32r(v.x); Bs[0][k][bn4 + 1] = tf32r(v.y);
        Bs[0][k][bn4 + 2] = tf32r(v.z); Bs[0][k][bn4 + 3] = tf32r(v.w);
    }
    __syncthreads();

    float4 pa[2], pb[2];
    for (int t = 0; t < nk; ++t) {
        int buf = t & 1;
        if (t + 1 < nk) {
            int kb = kbeg + (t + 1) * BK;
            #pragma unroll
            for (int l = 0; l < 2; ++l)
                pa[l] = *(const float4*)&A[(size_t)rows[am + l * 64] * lda + kb + af4];
            #pragma unroll
            for (int l = 0; l < 2; ++l)
                pb[l] = *(const float4*)&Bp[(size_t)(kb + bk + l * 8) * ldb + nb + bn4];
        }
        // compute on buf
        #pragma unroll
        for (int kk = 0; kk < BK; kk += 8) {
            uint32_t afr[2][4], bfr[8][2];
            #pragma unroll
            for (int mt = 0; mt < 2; ++mt) {
                int rb = wm * 32 + mt * 16 + gq;
                afr[mt][0] = __float_as_uint(As[buf][kk + tig][rb]);
                afr[mt][1] = __float_as_uint(As[buf][kk + tig][rb + 8]);
                afr[mt][2] = __float_as_uint(As[buf][kk + tig + 4][rb]);
                afr[mt][3] = __float_as_uint(As[buf][kk + tig + 4][rb + 8]);
            }
            #pragma unroll
            for (int nt = 0; nt < 8; ++nt) {
                int cb = wn * 64 + nt * 8 + gq;
                bfr[nt][0] = __float_as_uint(Bs[buf][kk + tig][cb]);
                bfr[nt][1] = __float_as_uint(Bs[buf][kk + tig + 4][cb]);
            }
            #pragma unroll
            for (int mt = 0; mt < 2; ++mt)
                #pragma unroll
                for (int nt = 0; nt < 8; ++nt)
                    mma_tf32(acc[mt][nt], afr[mt], bfr[nt]);
        }
        if (t + 1 < nk) {
            int nbuf = buf ^ 1;
            #pragma unroll
            for (int l = 0; l < 2; ++l) {
                int m = am + l * 64;
                As[nbuf][af4 + 0][m] = tf32r(pa[l].x);
                As[nbuf][af4 + 1][m] = tf32r(pa[l].y);
                As[nbuf][af4 + 2][m] = tf32r(pa[l].z);
                As[nbuf][af4 + 3][m] = tf32r(pa[l].w);
            }
            #pragma unroll
            for (int l = 0; l < 2; ++l) {
                int k = bk + l * 8;
                Bs[nbuf][k][bn4 + 0] = tf32r(pb[l].x);
                Bs[nbuf][k][bn4 + 1] = tf32r(pb[l].y);
                Bs[nbuf][k][bn4 + 2] = tf32r(pb[l].z);
                Bs[nbuf][k][bn4 + 3] = tf32r(pb[l].w);
            }
        }
        __syncthreads();
    }

    // epilogue
    #pragma unroll
    for (int mt = 0; mt < 2; ++mt) {
        #pragma unroll
        for (int half = 0; half < 2; ++half) {
            int r  = wm * 32 + mt * 16 + half * 8 + gq;
            int gi = i0 + r;
            if (gi >= iend) continue;
            int orow = (EPI == 2) ? g_perm[gi] : gi;
            size_t rowoff = (size_t)orow * ldc + nb;
            size_t growoff = (size_t)gi * ldc + nb;
            #pragma unroll
            for (int nt = 0; nt < 8; ++nt) {
                int cc = wn * 64 + nt * 8 + 2 * tig;
                float v0 = acc[mt][nt][half * 2 + 0];
                float v1 = acc[mt][nt][half * 2 + 1];
                if (EPI == 0) {
                    *(float2*)&C[rowoff + cc] = make_float2(v0, v1);
                } else if (EPI == 1) {
                    float2 gv = *(const float2*)&Gbuf[growoff + cc];
                    float o0 = v0 * gv.x / (1.f + __expf(-gv.x));
                    float o1 = v1 * gv.y / (1.f + __expf(-gv.y));
                    *(float2*)&C[rowoff + cc] = make_float2(o0, o1);
                } else {
                    const float* bp = bias + (size_t)e * DH + nb + cc;
                    *(float2*)&C[rowoff + cc] = make_float2(v0 + bp[0], v1 + bp[1]);
                }
            }
        }
    }
}

// ===================== split-K reduce =======================================
template<int S>
__global__ void reduce_k(const float4* __restrict__ P, float4* __restrict__ O,
                         int n4, size_t stride4)
{
    int i = blockIdx.x * 256 + threadIdx.x;
    if (i >= n4) return;
    float4 s = P[i];
    #pragma unroll
    for (int k = 1; k < S; ++k) {
        float4 v = P[(size_t)k * stride4 + i];
        s.x += v.x; s.y += v.y; s.z += v.z; s.w += v.w;
    }
    O[i] = s;
}

// ===================== launch ================================================
extern "C" void kernel_launch(void* const* d_in, const int* in_sizes, int n_in,
                              void* d_out, int out_size)
{
    const float* x         = (const float*)d_in[0];
    const int*   eidx      = (const int*)  d_in[1];
    const float* gate_A    = (const float*)d_in[2];
    const float* gate_C    = (const float*)d_in[3];
    const float* gate_B    = (const float*)d_in[4];
    const float* up_A      = (const float*)d_in[5];
    const float* up_C      = (const float*)d_in[6];
    const float* up_B      = (const float*)d_in[7];
    const float* down_A    = (const float*)d_in[8];
    const float* down_C    = (const float*)d_in[9];
    const float* down_B    = (const float*)d_in[10];
    const float* down_bias = (const float*)d_in[11];
    float* out = (float*)d_out;

    float *pW1, *pW3, *pBg, *pBu, *pBd, *pH, *pG, *pY, *pHd, *pP1, *pP3;
    cudaGetSymbolAddress((void**)&pW1, g_W1);
    cudaGetSymbolAddress((void**)&pW3, g_W3);
    cudaGetSymbolAddress((void**)&pBg, g_Bgt);
    cudaGetSymbolAddress((void**)&pBu, g_But);
    cudaGetSymbolAddress((void**)&pBd, g_Bdt);
    cudaGetSymbolAddress((void**)&pH,  g_H);
    cudaGetSymbolAddress((void**)&pG,  g_G);
    cudaGetSymbolAddress((void**)&pY,  g_Y);
    cudaGetSymbolAddress((void**)&pHd, g_Hd);
    cudaGetSymbolAddress((void**)&pP1, g_P1);
    cudaGetSymbolAddress((void**)&pP3, g_P3);

    // permutation
    k_init<<<1, 32>>>();
    k_hist<<<NT / 256, 256>>>(eidx);
    k_scan<<<1, 1>>>();
    k_scatter<<<NT / 256, 256>>>(eidx);

    // weight precompute (tf32-rounded outputs)
    fuse_CA_T<DH><<<dim3(DH / 32, 2, NE), 256>>>(gate_A, gate_C, pW1, 256, 0);
    fuse_CA_T<DH><<<dim3(DH / 32, 2, NE), 256>>>(up_A,   up_C,   pW1, 256, 128);
    fuse_CA_T<DI><<<dim3(DI / 32, 2, NE), 256>>>(down_A, down_C, pW3, 128, 0);
    transpose_B<DI><<<dim3(DI / 32, 4, NE), dim3(32, 8)>>>(gate_B, pBg);
    transpose_B<DI><<<dim3(DI / 32, 4, NE), dim3(32, 8)>>>(up_B,   pBu);
    transpose_B<DH><<<dim3(DH / 32, 4, NE), dim3(32, 8)>>>(down_B, pBd);

    // K1: H[T,256] = x_perm @ W1   (split-K 4)
    mma_gemm<true, 0, 4><<<dim3(2, NT / 128, NE * 4), 256>>>(
        x, DH, pW1, 256, (size_t)DH * 256, DH,
        pP1, 256, (size_t)NT * 256, nullptr, nullptr);
    reduce_k<4><<<(NT * 256 / 4 + 255) / 256, 256>>>(
        (const float4*)pP1, (float4*)pH, NT * 256 / 4, (size_t)NT * 256 / 4);

    // K2a: G = Hg @ Bg^T
    mma_gemm<false, 0, 1><<<dim3(DI / 128, NT / 128, NE), 256>>>(
        pH, 256, pBg, DI, (size_t)NR * DI, NR,
        pG, DI, 0, nullptr, nullptr);
    // K2b: Y = silu(G) * (Hu @ Bu^T)
    mma_gemm<false, 1, 1><<<dim3(DI / 128, NT / 128, NE), 256>>>(
        pH + 128, 256, pBu, DI, (size_t)NR * DI, NR,
        pY, DI, 0, pG, nullptr);

    // K3: Hd = Y @ W3   (split-K 8)
    mma_gemm<false, 0, 8><<<dim3(1, NT / 128, NE * 8), 256>>>(
        pY, DI, pW3, 128, (size_t)DI * NR, DI,
        pP3, NR, (size_t)NT * NR, nullptr, nullptr);
    reduce_k<8><<<(NT * NR / 4 + 255) / 256, 256>>>(
        (const float4*)pP3, (float4*)pHd, NT * NR / 4, (size_t)NT * NR / 4);

    // K4: out[perm[i],:] = Hd @ Bd^T + bias[e]
    mma_gemm<false, 2, 1><<<dim3(DH / 128, NT / 128, NE), 256>>>(
        pHd, NR, pBd, DH, (size_t)NR * DH, NR,
        out, DH, 0, nullptr, down_bias);
}

// round 5
// speedup vs baseline: 4.6283x; 1.7936x over previous
#include <cuda_runtime.h>
#include <cuda_bf16.h>
#include <cstdint>

#define NE 8
#define NT 4096
#define DH 2048
#define DI 5632
#define NR 128
#define PITCH 80          // bytes per 32-bf16 smem row (conflict-free, 16B-aligned)
#define ABUF 10240        // 128 rows * 80B
#define BBUF 10240
#define BBUF2 5120        // 64 rows * 80B

// ===================== low-level helpers ====================================
__device__ __forceinline__ uint32_t smem_u32(const void* p) {
    uint32_t a;
    asm("{ .reg .u64 t; cvta.to.shared.u64 t, %1; cvt.u32.u64 %0, t; }"
        : "=r"(a) : "l"(p));
    return a;
}
__device__ __forceinline__ uint32_t lds32(uint32_t a) {
    uint32_t v;
    asm volatile("ld.shared.b32 %0, [%1];" : "=r"(v) : "r"(a));
    return v;
}
#define CP16(dst, src) \
    asm volatile("cp.async.cg.shared.global [%0], [%1], 16;" \
                 :: "r"(dst), "l"(src) : "memory")
#define CPCOMMIT() asm volatile("cp.async.commit_group;" ::: "memory")
#define CPWAIT(n)  asm volatile("cp.async.wait_group %0;" :: "n"(n) : "memory")

__device__ __forceinline__ void mma_bf16(
    float c[4], const uint32_t a[4], const uint32_t b[2])
{
    asm volatile(
        "mma.sync.aligned.m16n8k16.row.col.f32.bf16.bf16.f32 "
        "{%0,%1,%2,%3}, {%4,%5,%6,%7}, {%8,%9}, {%0,%1,%2,%3};"
        : "+f"(c[0]), "+f"(c[1]), "+f"(c[2]), "+f"(c[3])
        : "r"(a[0]), "r"(a[1]), "r"(a[2]), "r"(a[3]),
          "r"(b[0]), "r"(b[1]));
}

// ===================== scratch globals ======================================
__device__ int g_counts[NE];
__device__ int g_offsets[NE + 1];
__device__ int g_cursor[NE];
__device__ int g_perm[NT];

__device__ __nv_bfloat16 g_Xb [NT * DH];        // x bf16
__device__ __nv_bfloat16 g_W1 [NE * 256 * DH];  // [e][256][DH]: rows 0..127 gate_A, 128..255 up_A
__device__ __nv_bfloat16 g_Ad [NE * NR * DI];   // down_A bf16 [e][r][di]
__device__ __nv_bfloat16 g_Bg [NE * DI * NR];   // gate_B bf16 [e][di][r]
__device__ __nv_bfloat16 g_Bu [NE * DI * NR];   // up_B bf16
__device__ __nv_bfloat16 g_Bd [NE * DH * NR];   // down_B bf16 [e][dh][r]
__device__ __nv_bfloat16 g_W2 [256 * 256];      // block-diag [gate_C 0; 0 up_C]
__device__ __nv_bfloat16 g_Cd [NR * NR];        // down_C bf16
__device__ __nv_bfloat16 g_H  [NT * 256];       // low-rank pre-C
__device__ __nv_bfloat16 g_H2 [NT * 256];       // after C
__device__ __nv_bfloat16 g_Y  [NT * DI];        // swiglu output
__device__ __nv_bfloat16 g_Hd [NT * NR];
__device__ __nv_bfloat16 g_Hd2[NT * NR];
__device__ float g_P1[4 * NT * 256];
__device__ float g_P3[8 * NT * NR];

// ===================== permutation ==========================================
__global__ void k_init() {
    int i = threadIdx.x;
    if (i < NE) { g_counts[i] = 0; g_cursor[i] = 0; }
}
__global__ void k_hist(const int* __restrict__ idx) {
    int t = blockIdx.x * 256 + threadIdx.x;
    if (t < NT) atomicAdd(&g_counts[idx[t]], 1);
}
__global__ void k_scan() {
    if (threadIdx.x == 0) {
        int s = 0;
        for (int e = 0; e < NE; ++e) { g_offsets[e] = s; s += g_counts[e]; }
        g_offsets[NE] = s;
    }
}
__global__ void k_scatter(const int* __restrict__ idx) {
    int t = blockIdx.x * 256 + threadIdx.x;
    if (t < NT) {
        int e = idx[t];
        int p = atomicAdd(&g_cursor[e], 1);
        g_perm[g_offsets[e] + p] = t;
    }
}

// ===================== fp32 -> bf16 conversions =============================
__global__ void f2bf(const float4* __restrict__ s, uint2* __restrict__ d, int n4) {
    int i = blockIdx.x * 256 + threadIdx.x;
    if (i < n4) {
        float4 v = s[i];
        __nv_bfloat162 lo = __floats2bfloat162_rn(v.x, v.y);
        __nv_bfloat162 hi = __floats2bfloat162_rn(v.z, v.w);
        uint2 o;
        o.x = *(uint32_t*)&lo;
        o.y = *(uint32_t*)&hi;
        d[i] = o;
    }
}
// packs per-expert chunks into strided destination (for W1 assembly)
__global__ void f2bf_pack(const float4* __restrict__ s, __nv_bfloat16* __restrict__ d,
                          int chunk4, size_t dstStrideE, size_t dstOff) {
    int i = blockIdx.x * 256 + threadIdx.x;
    if (i < NE * chunk4) {
        int e = i / chunk4, off = i % chunk4;
        float4 v = s[i];
        __nv_bfloat162 lo = __floats2bfloat162_rn(v.x, v.y);
        __nv_bfloat162 hi = __floats2bfloat162_rn(v.z, v.w);
        uint2* dp = (uint2*)(d + (size_t)e * dstStrideE + dstOff + (size_t)off * 4);
        uint2 o; o.x = *(uint32_t*)&lo; o.y = *(uint32_t*)&hi;
        *dp = o;
    }
}
// W2 block-diagonal: [256][256]; rows 0..127 gate_C, rows 128..255 up_C
__global__ void build_W2(const float* __restrict__ Cg, const float* __restrict__ Cu,
                         __nv_bfloat16* __restrict__ W2) {
    int i = blockIdx.x * 256 + threadIdx.x;
    if (i < 256 * 256) {
        int n = i >> 8, k = i & 255;
        float v = 0.f;
        if (n < 128 && k < 128) v = Cg[n * 128 + k];
        else if (n >= 128 && k >= 128) v = Cu[(n - 128) * 128 + (k - 128)];
        W2[i] = __float2bfloat16(v);
    }
}

// ===================== bf16 MMA GEMM (single stream) ========================
// D[i][n] = sum_k A[i][k] * B[n][k].  BM=128, BN=128, BK=32, cp.async dbl-buf.
// EPI 0: fp32 store (+split offset). EPI 2: fp32 +bias +perm scatter. EPI 3: bf16.
template<bool GATHER, bool WEIGHTS, int EPI, int SPLITK>
__global__ void __launch_bounds__(256, 2) mma1(
    const __nv_bfloat16* __restrict__ A, int lda, size_t strideAe, int Mtot,
    const __nv_bfloat16* __restrict__ B, int ldb, size_t strideBe, int Ktot,
    void* __restrict__ outp, int ldc, size_t splitStride,
    const float* __restrict__ bias)
{
    extern __shared__ char dsm[];
    uint32_t sb = smem_u32(dsm);
    uint32_t sA = sb, sB = sb + 2 * ABUF;
    int* rows = (int*)(dsm + 4 * ABUF);

    int z = blockIdx.z;
    int e, base, iend;
    if (WEIGHTS) { e = z; base = 0; iend = Mtot; }
    else {
        e = z / SPLITK;
        base = g_offsets[e]; iend = g_offsets[e + 1];
    }
    int sk = WEIGHTS ? 0 : (z % SPLITK);
    int i0 = base + blockIdx.y * 128;
    if (i0 >= iend) return;
    int nb = blockIdx.x * 128;
    int tid = threadIdx.x;

    if (tid < 128) {
        int i = i0 + tid; if (i >= iend) i = iend - 1;
        rows[tid] = GATHER ? g_perm[i] : i;
    }
    __syncthreads();

    const __nv_bfloat16* Ap = A + (WEIGHTS ? (size_t)e * strideAe : 0);
    const __nv_bfloat16* Bp = B + (size_t)e * strideBe;

    int kstep = Ktot / SPLITK;
    int kbeg  = sk * kstep;
    int nk    = kstep / 32;

    int lane = tid & 31, wid = tid >> 5;
    int wm = wid >> 1, wn = wid & 1;
    int gq = lane >> 2, tig = lane & 3;

    float acc[2][8][4];
    #pragma unroll
    for (int mt = 0; mt < 2; ++mt)
        #pragma unroll
        for (int nt = 0; nt < 8; ++nt)
            #pragma unroll
            for (int j = 0; j < 4; ++j) acc[mt][nt][j] = 0.f;

    // staging lambda (manual): 512 A-chunks + 512 B-chunks, 2+2 per thread
    int r0i = tid >> 2, ch0 = (tid & 3);
    // prologue
    {
        #pragma unroll
        for (int l = 0; l < 2; ++l) {
            int idx = tid + l * 256;
            int r = idx >> 2, ch = idx & 3;
            CP16(sA + r * PITCH + ch * 16,
                 Ap + (size_t)rows[r] * lda + kbeg + ch * 8);
        }
        #pragma unroll
        for (int l = 0; l < 2; ++l) {
            int idx = tid + l * 256;
            int n = idx >> 2, ch = idx & 3;
            CP16(sB + n * PITCH + ch * 16,
                 Bp + (size_t)(nb + n) * ldb + kbeg + ch * 8);
        }
        CPCOMMIT();
    }

    for (int t = 0; t < nk; ++t) {
        int buf = t & 1;
        if (t + 1 < nk) {
            int kb = kbeg + (t + 1) * 32;
            int nbuf = buf ^ 1;
            #pragma unroll
            for (int l = 0; l < 2; ++l) {
                int idx = tid + l * 256;
                int r = idx >> 2, ch = idx & 3;
                CP16(sA + nbuf * ABUF + r * PITCH + ch * 16,
                     Ap + (size_t)rows[r] * lda + kb + ch * 8);
            }
            #pragma unroll
            for (int l = 0; l < 2; ++l) {
                int idx = tid + l * 256;
                int n = idx >> 2, ch = idx & 3;
                CP16(sB + nbuf * BBUF + n * PITCH + ch * 16,
                     Bp + (size_t)(nb + n) * ldb + kb + ch * 8);
            }
            CPCOMMIT();
            CPWAIT(1);
        } else {
            CPWAIT(0);
        }
        __syncthreads();

        #pragma unroll
        for (int ks = 0; ks < 2; ++ks) {
            uint32_t a[2][4], b[8][2];
            uint32_t ab = sA + buf * ABUF + (wm * 32 + gq) * PITCH + ks * 32 + tig * 4;
            #pragma unroll
            for (int mt = 0; mt < 2; ++mt) {
                uint32_t p = ab + mt * 16 * PITCH;
                a[mt][0] = lds32(p);
                a[mt][1] = lds32(p + 8 * PITCH);
                a[mt][2] = lds32(p + 16);
                a[mt][3] = lds32(p + 8 * PITCH + 16);
            }
            uint32_t bb = sB + buf * BBUF + (wn * 64 + gq) * PITCH + ks * 32 + tig * 4;
            #pragma unroll
            for (int nt = 0; nt < 8; ++nt) {
                b[nt][0] = lds32(bb + nt * 8 * PITCH);
                b[nt][1] = lds32(bb + nt * 8 * PITCH + 16);
            }
            #pragma unroll
            for (int mt = 0; mt < 2; ++mt)
                #pragma unroll
                for (int nt = 0; nt < 8; ++nt)
                    mma_bf16(acc[mt][nt], a[mt], b[nt]);
        }
        __syncthreads();
    }

    // epilogue
    float* Cf = (float*)outp;
    __nv_bfloat16* Cb = (__nv_bfloat16*)outp;
    if (EPI == 0) Cf += (size_t)sk * splitStride;
    if (EPI == 3 && WEIGHTS) Cb += (size_t)e * (size_t)Mtot * ldc;

    #pragma unroll
    for (int mt = 0; mt < 2; ++mt) {
        #pragma unroll
        for (int half = 0; half < 2; ++half) {
            int r = wm * 32 + mt * 16 + half * 8 + gq;
            int gi = i0 + r;
            if (gi >= iend) continue;
            int orow = (EPI == 2) ? g_perm[gi] : gi;
            size_t rowoff = (size_t)orow * ldc + nb;
            #pragma unroll
            for (int nt = 0; nt < 8; ++nt) {
                int cc = wn * 64 + nt * 8 + 2 * tig;
                float v0 = acc[mt][nt][half * 2 + 0];
                float v1 = acc[mt][nt][half * 2 + 1];
                if (EPI == 0) {
                    *(float2*)&Cf[rowoff + cc] = make_float2(v0, v1);
                } else if (EPI == 2) {
                    const float* bp = bias + (size_t)e * DH + nb + cc;
                    *(float2*)&Cf[rowoff + cc] = make_float2(v0 + bp[0], v1 + bp[1]);
                } else {
                    __nv_bfloat162 o = __floats2bfloat162_rn(v0, v1);
                    *(uint32_t*)&Cb[rowoff + cc] = *(uint32_t*)&o;
                }
            }
        }
    }
}

// ===================== fused gate/up GEMM + SwiGLU ==========================
// BM=128, BN=64 (per stream), BK=32, K=128.  A = H2 (gate cols 0..127, up 128..255)
__global__ void __launch_bounds__(256, 2) mma2(
    const __nv_bfloat16* __restrict__ H2,
    const __nv_bfloat16* __restrict__ Bgw, const __nv_bfloat16* __restrict__ Buw,
    __nv_bfloat16* __restrict__ Y)
{
    extern __shared__ char dsm[];
    uint32_t sb = smem_u32(dsm);
    uint32_t sAg = sb, sAu = sb + 2 * ABUF;
    uint32_t sBg = sb + 4 * ABUF, sBu = sb + 4 * ABUF + 2 * BBUF2;

    int e = blockIdx.z;
    int base = g_offsets[e], iend = g_offsets[e + 1];
    int i0 = base + blockIdx.y * 128;
    if (i0 >= iend) return;
    int nb = blockIdx.x * 64;
    int tid = threadIdx.x;

    const __nv_bfloat16* Bg = Bgw + (size_t)e * DI * NR;
    const __nv_bfloat16* Bu = Buw + (size_t)e * DI * NR;

    int lane = tid & 31, wid = tid >> 5;
    int wm = wid >> 1, wn = wid & 1;
    int gq = lane >> 2, tig = lane & 3;

    float accG[2][4][4], accU[2][4][4];
    #pragma unroll
    for (int mt = 0; mt < 2; ++mt)
        #pragma unroll
        for (int nt = 0; nt < 4; ++nt)
            #pragma unroll
            for (int j = 0; j < 4; ++j) { accG[mt][nt][j] = 0.f; accU[mt][nt][j] = 0.f; }

    // stage: A 2 streams x 512 chunks (4/thread); B 2 x 256 (2/thread)
    const int nk = 4;  // K=128 / 32
    auto rowOf = [&](int r) { int i = i0 + r; return (i < iend) ? i : (iend - 1); };

    {
        #pragma unroll
        for (int l = 0; l < 4; ++l) {
            int idx = tid + l * 256;            // 0..1023
            int st = idx >> 9, rr = (idx >> 2) & 127, ch = idx & 3;
            uint32_t dst = (st ? sAu : sAg) + rr * PITCH + ch * 16;
            CP16(dst, H2 + (size_t)rowOf(rr) * 256 + st * 128 + 0 + ch * 8);
        }
        #pragma unroll
        for (int l = 0; l < 2; ++l) {
            int idx = tid + l * 256;            // 0..511
            int st = idx >> 8, n = (idx >> 2) & 63, ch = idx & 3;
            const __nv_bfloat16* src = (st ? Bu : Bg) + (size_t)(nb + n) * NR + 0 + ch * 8;
            uint32_t dst = (st ? sBu : sBg) + n * PITCH + ch * 16;
            CP16(dst, src);
        }
        CPCOMMIT();
    }

    for (int t = 0; t < nk; ++t) {
        int buf = t & 1;
        if (t + 1 < nk) {
            int kb = (t + 1) * 32;
            int nbuf = buf ^ 1;
            #pragma unroll
            for (int l = 0; l < 4; ++l) {
                int idx = tid + l * 256;
                int st = idx >> 9, rr = (idx >> 2) & 127, ch = idx & 3;
                uint32_t dst = (st ? sAu : sAg) + nbuf * ABUF + rr * PITCH + ch * 16;
                CP16(dst, H2 + (size_t)rowOf(rr) * 256 + st * 128 + kb + ch * 8);
            }
            #pragma unroll
            for (int l = 0; l < 2; ++l) {
                int idx = tid + l * 256;
                int st = idx >> 8, n = (idx >> 2) & 63, ch = idx & 3;
                const __nv_bfloat16* src = (st ? Bu : Bg) + (size_t)(nb + n) * NR + kb + ch * 8;
                uint32_t dst = (st ? sBu : sBg) + nbuf * BBUF2 + n * PITCH + ch * 16;
                CP16(dst, src);
            }
            CPCOMMIT();
            CPWAIT(1);
        } else {
            CPWAIT(0);
        }
        __syncthreads();

        #pragma unroll
        for (int ks = 0; ks < 2; ++ks) {
            uint32_t ag[2][4], au[2][4], bg[4][2], bu[4][2];
            uint32_t abg = sAg + buf * ABUF + (wm * 32 + gq) * PITCH + ks * 32 + tig * 4;
            uint32_t abu = sAu + buf * ABUF + (wm * 32 + gq) * PITCH + ks * 32 + tig * 4;
            #pragma unroll
            for (int mt = 0; mt < 2; ++mt) {
                uint32_t pg = abg + mt * 16 * PITCH;
                ag[mt][0] = lds32(pg);
                ag[mt][1] = lds32(pg + 8 * PITCH);
                ag[mt][2] = lds32(pg + 16);
                ag[mt][3] = lds32(pg + 8 * PITCH + 16);
                uint32_t pu = abu + mt * 16 * PITCH;
                au[mt][0] = lds32(pu);
                au[mt][1] = lds32(pu + 8 * PITCH);
                au[mt][2] = lds32(pu + 16);
                au[mt][3] = lds32(pu + 8 * PITCH + 16);
            }
            uint32_t bbg = sBg + buf * BBUF2 + (wn * 32 + gq) * PITCH + ks * 32 + tig * 4;
            uint32_t bbu = sBu + buf * BBUF2 + (wn * 32 + gq) * PITCH + ks * 32 + tig * 4;
            #pragma unroll
            for (int nt = 0; nt < 4; ++nt) {
                bg[nt][0] = lds32(bbg + nt * 8 * PITCH);
                bg[nt][1] = lds32(bbg + nt * 8 * PITCH + 16);
                bu[nt][0] = lds32(bbu + nt * 8 * PITCH);
                bu[nt][1] = lds32(bbu + nt * 8 * PITCH + 16);
            }
            #pragma unroll
            for (int mt = 0; mt < 2; ++mt)
                #pragma unroll
                for (int nt = 0; nt < 4; ++nt) {
                    mma_bf16(accG[mt][nt], ag[mt], bg[nt]);
                    mma_bf16(accU[mt][nt], au[mt], bu[nt]);
                }
        }
        __syncthreads();
    }

    // swiglu epilogue -> Y bf16
    #pragma unroll
    for (int mt = 0; mt < 2; ++mt) {
        #pragma unroll
        for (int half = 0; half < 2; ++half) {
            int r = wm * 32 + mt * 16 + half * 8 + gq;
            int gi = i0 + r;
            if (gi >= iend) continue;
            size_t rowoff = (size_t)gi * DI + nb;
            #pragma unroll
            for (int nt = 0; nt < 4; ++nt) {
                int cc = wn * 32 + nt * 8 + 2 * tig;
                float g0 = accG[mt][nt][half * 2 + 0];
                float g1 = accG[mt][nt][half * 2 + 1];
                float u0 = accU[mt][nt][half * 2 + 0];
                float u1 = accU[mt][nt][half * 2 + 1];
                float y0 = u0 * g0 / (1.f + __expf(-g0));
                float y1 = u1 * g1 / (1.f + __expf(-g1));
                __nv_bfloat162 o = __floats2bfloat162_rn(y0, y1);
                *(uint32_t*)&Y[rowoff + cc] = *(uint32_t*)&o;
            }
        }
    }
}

// ===================== split-K reduce -> bf16 ================================
template<int S>
__global__ void reduce_bf(const float4* __restrict__ P, uint2* __restrict__ O,
                          int n4, size_t stride4)
{
    int i = blockIdx.x * 256 + threadIdx.x;
    if (i >= n4) return;
    float4 s = P[i];
    #pragma unroll
    for (int k = 1; k < S; ++k) {
        float4 v = P[(size_t)k * stride4 + i];
        s.x += v.x; s.y += v.y; s.z += v.z; s.w += v.w;
    }
    __nv_bfloat162 lo = __floats2bfloat162_rn(s.x, s.y);
    __nv_bfloat162 hi = __floats2bfloat162_rn(s.z, s.w);
    uint2 o; o.x = *(uint32_t*)&lo; o.y = *(uint32_t*)&hi;
    O[i] = o;
}

// ===================== launch ================================================
extern "C" void kernel_launch(void* const* d_in, const int* in_sizes, int n_in,
                              void* d_out, int out_size)
{
    const float* x         = (const float*)d_in[0];
    const int*   eidx      = (const int*)  d_in[1];
    const float* gate_A    = (const float*)d_in[2];
    const float* gate_C    = (const float*)d_in[3];
    const float* gate_B    = (const float*)d_in[4];
    const float* up_A      = (const float*)d_in[5];
    const float* up_C      = (const float*)d_in[6];
    const float* up_B      = (const float*)d_in[7];
    const float* down_A    = (const float*)d_in[8];
    const float* down_C    = (const float*)d_in[9];
    const float* down_B    = (const float*)d_in[10];
    const float* down_bias = (const float*)d_in[11];
    float* out = (float*)d_out;

    __nv_bfloat16 *pXb, *pW1, *pAd, *pBg, *pBu, *pBd, *pW2, *pCd,
                  *pH, *pH2, *pY, *pHd, *pHd2;
    float *pP1, *pP3;
    cudaGetSymbolAddress((void**)&pXb,  g_Xb);
    cudaGetSymbolAddress((void**)&pW1,  g_W1);
    cudaGetSymbolAddress((void**)&pAd,  g_Ad);
    cudaGetSymbolAddress((void**)&pBg,  g_Bg);
    cudaGetSymbolAddress((void**)&pBu,  g_Bu);
    cudaGetSymbolAddress((void**)&pBd,  g_Bd);
    cudaGetSymbolAddress((void**)&pW2,  g_W2);
    cudaGetSymbolAddress((void**)&pCd,  g_Cd);
    cudaGetSymbolAddress((void**)&pH,   g_H);
    cudaGetSymbolAddress((void**)&pH2,  g_H2);
    cudaGetSymbolAddress((void**)&pY,   g_Y);
    cudaGetSymbolAddress((void**)&pHd,  g_Hd);
    cudaGetSymbolAddress((void**)&pHd2, g_Hd2);
    cudaGetSymbolAddress((void**)&pP1,  g_P1);
    cudaGetSymbolAddress((void**)&pP3,  g_P3);

    const int SM1 = 4 * ABUF + 1024;               // 41984
    const int SM2 = 4 * ABUF + 4 * BBUF2 + 512;    // 61952
    cudaFuncSetAttribute(mma1<true,  false, 0, 4>, cudaFuncAttributeMaxDynamicSharedMemorySize, SM1);
    cudaFuncSetAttribute(mma1<false, true,  3, 1>, cudaFuncAttributeMaxDynamicSharedMemorySize, SM1);
    cudaFuncSetAttribute(mma1<false, false, 0, 8>, cudaFuncAttributeMaxDynamicSharedMemorySize, SM1);
    cudaFuncSetAttribute(mma1<false, false, 2, 1>, cudaFuncAttributeMaxDynamicSharedMemorySize, SM1);
    cudaFuncSetAttribute(mma2, cudaFuncAttributeMaxDynamicSharedMemorySize, SM2);

    // permutation
    k_init<<<1, 32>>>();
    k_hist<<<NT / 256, 256>>>(eidx);
    k_scan<<<1, 1>>>();
    k_scatter<<<NT / 256, 256>>>(eidx);

    // conversions
    f2bf<<<(NT * DH / 4 + 255) / 256, 256>>>((const float4*)x, (uint2*)pXb, NT * DH / 4);
    f2bf_pack<<<(NE * 128 * DH / 4 + 255) / 256, 256>>>(
        (const float4*)gate_A, pW1, 128 * DH / 4, (size_t)256 * DH, 0);
    f2bf_pack<<<(NE * 128 * DH / 4 + 255) / 256, 256>>>(
        (const float4*)up_A, pW1, 128 * DH / 4, (size_t)256 * DH, (size_t)128 * DH);
    f2bf<<<(NE * NR * DI / 4 + 255) / 256, 256>>>((const float4*)down_A, (uint2*)pAd, NE * NR * DI / 4);
    f2bf<<<(NE * DI * NR / 4 + 255) / 256, 256>>>((const float4*)gate_B, (uint2*)pBg, NE * DI * NR / 4);
    f2bf<<<(NE * DI * NR / 4 + 255) / 256, 256>>>((const float4*)up_B,   (uint2*)pBu, NE * DI * NR / 4);
    f2bf<<<(NE * DH * NR / 4 + 255) / 256, 256>>>((const float4*)down_B, (uint2*)pBd, NE * DH * NR / 4);
    build_W2<<<(256 * 256 + 255) / 256, 256>>>(gate_C, up_C, pW2);
    f2bf<<<(NR * NR / 4 + 255) / 256, 256>>>((const float4*)down_C, (uint2*)pCd, NR * NR / 4);

    // K1: H = x_perm @ [gate_A; up_A]^T   (split-K 4)
    mma1<true, false, 0, 4><<<dim3(2, NT / 128, NE * 4), 256, SM1>>>(
        pXb, DH, 0, 0, pW1, DH, (size_t)256 * DH, DH,
        pP1, 256, (size_t)NT * 256, nullptr);
    reduce_bf<4><<<(NT * 256 / 4 + 255) / 256, 256>>>(
        (const float4*)pP1, (uint2*)pH, NT * 256 / 4, (size_t)NT * 256 / 4);

    // K1.5: H2 = H @ W2^T  (block-diag C; no expert logic)
    mma1<false, true, 3, 1><<<dim3(2, NT / 128, 1), 256, SM1>>>(
        pH, 256, 0, NT, pW2, 256, 0, 256,
        pH2, 256, 0, nullptr);

    // K2: Y = silu(H2g @ gate_B^T) * (H2u @ up_B^T)
    mma2<<<dim3(DI / 64, NT / 128, NE), 256, SM2>>>(pH2, pBg, pBu, pY);

    // K3: Hd = Y @ down_A^T   (split-K 8)
    mma1<false, false, 0, 8><<<dim3(1, NT / 128, NE * 8), 256, SM1>>>(
        pY, DI, 0, 0, pAd, DI, (size_t)NR * DI, DI,
        pP3, NR, (size_t)NT * NR, nullptr);
    reduce_bf<8><<<(NT * NR / 4 + 255) / 256, 256>>>(
        (const float4*)pP3, (uint2*)pHd, NT * NR / 4, (size_t)NT * NR / 4);

    // K3.5: Hd2 = Hd @ down_C^T
    mma1<false, true, 3, 1><<<dim3(1, NT / 128, 1), 256, SM1>>>(
        pHd, NR, 0, NT, pCd, NR, 0, NR,
        pHd2, NR, 0, nullptr);

    // K4: out[perm[i],:] = Hd2 @ down_B^T + bias[e]
    mma1<false, false, 2, 1><<<dim3(DH / 128, NT / 128, NE), 256, SM1>>>(
        pHd2, NR, 0, 0, pBd, NR, (size_t)DH * NR, NR,
        out, DH, 0, down_bias);
}

// round 6
// speedup vs baseline: 4.7713x; 1.0309x over previous
#include <cuda_runtime.h>
#include <cuda_bf16.h>
#include <cstdint>

#define NE 8
#define NT 4096
#define DH 2048
#define DI 5632
#define NR 128
#define PITCH 80          // bytes per 32-bf16 smem row (conflict-free for LDSM too)
#define ABUF 10240        // 128 rows * 80B
#define BBUF 10240
#define BBUF2 5120        // 64 rows * 80B

// ===================== low-level helpers ====================================
__device__ __forceinline__ uint32_t smem_u32(const void* p) {
    uint32_t a;
    asm("{ .reg .u64 t; cvta.to.shared.u64 t, %1; cvt.u32.u64 %0, t; }"
        : "=r"(a) : "l"(p));
    return a;
}
#define CP16(dst, src) \
    asm volatile("cp.async.cg.shared.global [%0], [%1], 16;" \
                 :: "r"(dst), "l"(src) : "memory")
#define CPCOMMIT() asm volatile("cp.async.commit_group;" ::: "memory")
#define CPWAIT(n)  asm volatile("cp.async.wait_group %0;" :: "n"(n) : "memory")

__device__ __forceinline__ void ldsm4(uint32_t r[4], uint32_t addr) {
    asm volatile("ldmatrix.sync.aligned.m8n8.x4.shared.b16 {%0,%1,%2,%3}, [%4];"
        : "=r"(r[0]), "=r"(r[1]), "=r"(r[2]), "=r"(r[3]) : "r"(addr));
}

__device__ __forceinline__ void mma_bf16(
    float c[4], const uint32_t a[4], const uint32_t b[2])
{
    asm volatile(
        "mma.sync.aligned.m16n8k16.row.col.f32.bf16.bf16.f32 "
        "{%0,%1,%2,%3}, {%4,%5,%6,%7}, {%8,%9}, {%0,%1,%2,%3};"
        : "+f"(c[0]), "+f"(c[1]), "+f"(c[2]), "+f"(c[3])
        : "r"(a[0]), "r"(a[1]), "r"(a[2]), "r"(a[3]),
          "r"(b[0]), "r"(b[1]));
}

// ===================== scratch globals ======================================
__device__ int g_counts[NE];
__device__ int g_offsets[NE + 1];
__device__ int g_cursor[NE];
__device__ int g_perm[NT];

__device__ __nv_bfloat16 g_Xb [NT * DH];
__device__ __nv_bfloat16 g_W1 [NE * 256 * DH];  // rows 0..127 gate_A, 128..255 up_A
__device__ __nv_bfloat16 g_Ad [NE * NR * DI];
__device__ __nv_bfloat16 g_Bg [NE * DI * NR];
__device__ __nv_bfloat16 g_Bu [NE * DI * NR];
__device__ __nv_bfloat16 g_Bd [NE * DH * NR];
__device__ __nv_bfloat16 g_W2 [256 * 256];      // block-diag [gate_C 0; 0 up_C]
__device__ __nv_bfloat16 g_Cd [NR * NR];
__device__ __nv_bfloat16 g_H  [NT * 256];
__device__ __nv_bfloat16 g_H2 [NT * 256];
__device__ __nv_bfloat16 g_Y  [NT * DI];
__device__ __nv_bfloat16 g_Hd [NT * NR];
__device__ __nv_bfloat16 g_Hd2[NT * NR];
__device__ float g_P1[4 * NT * 256];
__device__ float g_P3[8 * NT * NR];

// ===================== permutation ==========================================
__global__ void k_init() {
    int i = threadIdx.x;
    if (i < NE) { g_counts[i] = 0; g_cursor[i] = 0; }
}
__global__ void k_hist(const int* __restrict__ idx) {
    int t = blockIdx.x * 256 + threadIdx.x;
    if (t < NT) atomicAdd(&g_counts[idx[t]], 1);
}
__global__ void k_scan() {
    if (threadIdx.x == 0) {
        int s = 0;
        for (int e = 0; e < NE; ++e) { g_offsets[e] = s; s += g_counts[e]; }
        g_offsets[NE] = s;
    }
}
__global__ void k_scatter(const int* __restrict__ idx) {
    int t = blockIdx.x * 256 + threadIdx.x;
    if (t < NT) {
        int e = idx[t];
        int p = atomicAdd(&g_cursor[e], 1);
        g_perm[g_offsets[e] + p] = t;
    }
}

// ===================== fp32 -> bf16 conversions =============================
__global__ void f2bf(const float4* __restrict__ s, uint2* __restrict__ d, int n4) {
    int i = blockIdx.x * 256 + threadIdx.x;
    if (i < n4) {
        float4 v = s[i];
        __nv_bfloat162 lo = __floats2bfloat162_rn(v.x, v.y);
        __nv_bfloat162 hi = __floats2bfloat162_rn(v.z, v.w);
        uint2 o;
        o.x = *(uint32_t*)&lo;
        o.y = *(uint32_t*)&hi;
        d[i] = o;
    }
}
__global__ void f2bf_pack(const float4* __restrict__ s, __nv_bfloat16* __restrict__ d,
                          int chunk4, size_t dstStrideE, size_t dstOff) {
    int i = blockIdx.x * 256 + threadIdx.x;
    if (i < NE * chunk4) {
        int e = i / chunk4, off = i % chunk4;
        float4 v = s[i];
        __nv_bfloat162 lo = __floats2bfloat162_rn(v.x, v.y);
        __nv_bfloat162 hi = __floats2bfloat162_rn(v.z, v.w);
        uint2* dp = (uint2*)(d + (size_t)e * dstStrideE + dstOff + (size_t)off * 4);
        uint2 o; o.x = *(uint32_t*)&lo; o.y = *(uint32_t*)&hi;
        *dp = o;
    }
}
__global__ void build_W2(const float* __restrict__ Cg, const float* __restrict__ Cu,
                         __nv_bfloat16* __restrict__ W2) {
    int i = blockIdx.x * 256 + threadIdx.x;
    if (i < 256 * 256) {
        int n = i >> 8, k = i & 255;
        float v = 0.f;
        if (n < 128 && k < 128) v = Cg[n * 128 + k];
        else if (n >= 128 && k >= 128) v = Cu[(n - 128) * 128 + (k - 128)];
        W2[i] = __float2bfloat16(v);
    }
}

// ===================== bf16 MMA GEMM (ldmatrix fragments) ===================
// D[i][n] = sum_k A[i][k] * B[n][k].  BM=128, BN=128, BK=32, cp.async dbl-buf.
// EPI 0: fp32 store (+split offset). EPI 2: fp32 +bias +perm scatter. EPI 3: bf16.
template<bool GATHER, bool WEIGHTS, int EPI, int SPLITK>
__global__ void __launch_bounds__(256, 2) mma1(
    const __nv_bfloat16* __restrict__ A, int lda, size_t strideAe, int Mtot,
    const __nv_bfloat16* __restrict__ B, int ldb, size_t strideBe, int Ktot,
    void* __restrict__ outp, int ldc, size_t splitStride,
    const float* __restrict__ bias)
{
    extern __shared__ char dsm[];
    uint32_t sb = smem_u32(dsm);
    uint32_t sA = sb, sB = sb + 2 * ABUF;
    int* rows = (int*)(dsm + 4 * ABUF);

    int z = blockIdx.z;
    int e, base, iend;
    if (WEIGHTS) { e = z; base = 0; iend = Mtot; }
    else {
        e = z / SPLITK;
        base = g_offsets[e]; iend = g_offsets[e + 1];
    }
    int sk = WEIGHTS ? 0 : (z % SPLITK);
    int i0 = base + blockIdx.y * 128;
    if (i0 >= iend) return;
    int nb = blockIdx.x * 128;
    int tid = threadIdx.x;

    if (tid < 128) {
        int i = i0 + tid; if (i >= iend) i = iend - 1;
        rows[tid] = GATHER ? g_perm[i] : i;
    }
    __syncthreads();

    const __nv_bfloat16* Ap = A + (WEIGHTS ? (size_t)e * strideAe : 0);
    const __nv_bfloat16* Bp = B + (size_t)e * strideBe;

    int kstep = Ktot / SPLITK;
    int kbeg  = sk * kstep;
    int nk    = kstep / 32;

    int lane = tid & 31, wid = tid >> 5;
    int wm = wid >> 1, wn = wid & 1;
    int gq = lane >> 2, tig = lane & 3;
    int l7 = lane & 7, lb3 = (lane >> 3) & 1, lb4 = (lane >> 4) & 1;

    // ldmatrix lane base addresses (invariant except buf/ks/tile offsets)
    uint32_t aLane = sA + (uint32_t)(wm * 32 + l7 + lb3 * 8) * PITCH + lb4 * 16;
    uint32_t bLane = sB + (uint32_t)(wn * 64 + l7 + lb4 * 8) * PITCH + lb3 * 16;

    float acc[2][8][4];
    #pragma unroll
    for (int mt = 0; mt < 2; ++mt)
        #pragma unroll
        for (int nt = 0; nt < 8; ++nt)
            #pragma unroll
            for (int j = 0; j < 4; ++j) acc[mt][nt][j] = 0.f;

    // prologue
    {
        #pragma unroll
        for (int l = 0; l < 2; ++l) {
            int idx = tid + l * 256;
            int r = idx >> 2, ch = idx & 3;
            CP16(sA + r * PITCH + ch * 16,
                 Ap + (size_t)rows[r] * lda + kbeg + ch * 8);
        }
        #pragma unroll
        for (int l = 0; l < 2; ++l) {
            int idx = tid + l * 256;
            int n = idx >> 2, ch = idx & 3;
            CP16(sB + n * PITCH + ch * 16,
                 Bp + (size_t)(nb + n) * ldb + kbeg + ch * 8);
        }
        CPCOMMIT();
    }

    for (int t = 0; t < nk; ++t) {
        int buf = t & 1;
        if (t + 1 < nk) {
            int kb = kbeg + (t + 1) * 32;
            int nbuf = buf ^ 1;
            #pragma unroll
            for (int l = 0; l < 2; ++l) {
                int idx = tid + l * 256;
                int r = idx >> 2, ch = idx & 3;
                CP16(sA + nbuf * ABUF + r * PITCH + ch * 16,
                     Ap + (size_t)rows[r] * lda + kb + ch * 8);
            }
            #pragma unroll
            for (int l = 0; l < 2; ++l) {
                int idx = tid + l * 256;
                int n = idx >> 2, ch = idx & 3;
                CP16(sB + nbuf * BBUF + n * PITCH + ch * 16,
                     Bp + (size_t)(nb + n) * ldb + kb + ch * 8);
            }
            CPCOMMIT();
            CPWAIT(1);
        } else {
            CPWAIT(0);
        }
        __syncthreads();

        #pragma unroll
        for (int ks = 0; ks < 2; ++ks) {
            uint32_t a[2][4], b[8][2];
            uint32_t ab = aLane + buf * ABUF + ks * 32;
            #pragma unroll
            for (int mt = 0; mt < 2; ++mt)
                ldsm4(a[mt], ab + mt * 16 * PITCH);
            uint32_t bb = bLane + buf * BBUF + ks * 32;
            #pragma unroll
            for (int p = 0; p < 4; ++p) {
                uint32_t q[4];
                ldsm4(q, bb + p * 16 * PITCH);
                b[2 * p][0] = q[0]; b[2 * p][1] = q[1];
                b[2 * p + 1][0] = q[2]; b[2 * p + 1][1] = q[3];
            }
            #pragma unroll
            for (int mt = 0; mt < 2; ++mt)
                #pragma unroll
                for (int nt = 0; nt < 8; ++nt)
                    mma_bf16(acc[mt][nt], a[mt], b[nt]);
        }
        __syncthreads();
    }

    // epilogue
    float* Cf = (float*)outp;
    __nv_bfloat16* Cb = (__nv_bfloat16*)outp;
    if (EPI == 0) Cf += (size_t)sk * splitStride;
    if (EPI == 3 && WEIGHTS) Cb += (size_t)e * (size_t)Mtot * ldc;

    #pragma unroll
    for (int mt = 0; mt < 2; ++mt) {
        #pragma unroll
        for (int half = 0; half < 2; ++half) {
            int r = wm * 32 + mt * 16 + half * 8 + gq;
            int gi = i0 + r;
            if (gi >= iend) continue;
            int orow = (EPI == 2) ? g_perm[gi] : gi;
            size_t rowoff = (size_t)orow * ldc + nb;
            #pragma unroll
            for (int nt = 0; nt < 8; ++nt) {
                int cc = wn * 64 + nt * 8 + 2 * tig;
                float v0 = acc[mt][nt][half * 2 + 0];
                float v1 = acc[mt][nt][half * 2 + 1];
                if (EPI == 0) {
                    *(float2*)&Cf[rowoff + cc] = make_float2(v0, v1);
                } else if (EPI == 2) {
                    const float* bp = bias + (size_t)e * DH + nb + cc;
                    *(float2*)&Cf[rowoff + cc] = make_float2(v0 + bp[0], v1 + bp[1]);
                } else {
                    __nv_bfloat162 o = __floats2bfloat162_rn(v0, v1);
                    *(uint32_t*)&Cb[rowoff + cc] = *(uint32_t*)&o;
                }
            }
        }
    }
}

// ===================== fused gate/up GEMM + SwiGLU ==========================
// BM=128, BN=64 per stream, BK=32, K=128.
__global__ void __launch_bounds__(256, 2) mma2(
    const __nv_bfloat16* __restrict__ H2,
    const __nv_bfloat16* __restrict__ Bgw, const __nv_bfloat16* __restrict__ Buw,
    __nv_bfloat16* __restrict__ Y)
{
    extern __shared__ char dsm[];
    uint32_t sb = smem_u32(dsm);
    uint32_t sAg = sb, sAu = sb + 2 * ABUF;
    uint32_t sBg = sb + 4 * ABUF, sBu = sb + 4 * ABUF + 2 * BBUF2;

    int e = blockIdx.z;
    int base = g_offsets[e], iend = g_offsets[e + 1];
    int i0 = base + blockIdx.y * 128;
    if (i0 >= iend) return;
    int nb = blockIdx.x * 64;
    int tid = threadIdx.x;

    const __nv_bfloat16* Bg = Bgw + (size_t)e * DI * NR;
    const __nv_bfloat16* Bu = Buw + (size_t)e * DI * NR;

    int lane = tid & 31, wid = tid >> 5;
    int wm = wid >> 1, wn = wid & 1;
    int gq = lane >> 2, tig = lane & 3;
    int l7 = lane & 7, lb3 = (lane >> 3) & 1, lb4 = (lane >> 4) & 1;

    uint32_t aOffL = (uint32_t)(wm * 32 + l7 + lb3 * 8) * PITCH + lb4 * 16;
    uint32_t bOffL = (uint32_t)(wn * 32 + l7 + lb4 * 8) * PITCH + lb3 * 16;

    float accG[2][4][4], accU[2][4][4];
    #pragma unroll
    for (int mt = 0; mt < 2; ++mt)
        #pragma unroll
        for (int nt = 0; nt < 4; ++nt)
            #pragma unroll
            for (int j = 0; j < 4; ++j) { accG[mt][nt][j] = 0.f; accU[mt][nt][j] = 0.f; }

    const int nk = 4;  // K=128 / 32
    auto rowOf = [&](int r) { int i = i0 + r; return (i < iend) ? i : (iend - 1); };

    {
        #pragma unroll
        for (int l = 0; l < 4; ++l) {
            int idx = tid + l * 256;
            int st = idx >> 9, rr = (idx >> 2) & 127, ch = idx & 3;
            uint32_t dst = (st ? sAu : sAg) + rr * PITCH + ch * 16;
            CP16(dst, H2 + (size_t)rowOf(rr) * 256 + st * 128 + 0 + ch * 8);
        }
        #pragma unroll
        for (int l = 0; l < 2; ++l) {
            int idx = tid + l * 256;
            int st = idx >> 8, n = (idx >> 2) & 63, ch = idx & 3;
            const __nv_bfloat16* src = (st ? Bu : Bg) + (size_t)(nb + n) * NR + 0 + ch * 8;
            uint32_t dst = (st ? sBu : sBg) + n * PITCH + ch * 16;
            CP16(dst, src);
        }
        CPCOMMIT();
    }

    for (int t = 0; t < nk; ++t) {
        int buf = t & 1;
        if (t + 1 < nk) {
            int kb = (t + 1) * 32;
            int nbuf = buf ^ 1;
            #pragma unroll
            for (int l = 0; l < 4; ++l) {
                int idx = tid + l * 256;
                int st = idx >> 9, rr = (idx >> 2) & 127, ch = idx & 3;
                uint32_t dst = (st ? sAu : sAg) + nbuf * ABUF + rr * PITCH + ch * 16;
                CP16(dst, H2 + (size_t)rowOf(rr) * 256 + st * 128 + kb + ch * 8);
            }
            #pragma unroll
            for (int l = 0; l < 2; ++l) {
                int idx = tid + l * 256;
                int st = idx >> 8, n = (idx >> 2) & 63, ch = idx & 3;
                const __nv_bfloat16* src = (st ? Bu : Bg) + (size_t)(nb + n) * NR + kb + ch * 8;
                uint32_t dst = (st ? sBu : sBg) + nbuf * BBUF2 + n * PITCH + ch * 16;
                CP16(dst, src);
            }
            CPCOMMIT();
            CPWAIT(1);
        } else {
            CPWAIT(0);
        }
        __syncthreads();

        #pragma unroll
        for (int ks = 0; ks < 2; ++ks) {
            uint32_t ag[2][4], au[2][4], bg[4][2], bu[4][2];
            uint32_t abg = sAg + buf * ABUF + aOffL + ks * 32;
            uint32_t abu = sAu + buf * ABUF + aOffL + ks * 32;
            #pragma unroll
            for (int mt = 0; mt < 2; ++mt) {
                ldsm4(ag[mt], abg + mt * 16 * PITCH);
                ldsm4(au[mt], abu + mt * 16 * PITCH);
            }
            uint32_t bbg = sBg + buf * BBUF2 + bOffL + ks * 32;
            uint32_t bbu = sBu + buf * BBUF2 + bOffL + ks * 32;
            #pragma unroll
            for (int p = 0; p < 2; ++p) {
                uint32_t qg[4], qu[4];
                ldsm4(qg, bbg + p * 16 * PITCH);
                ldsm4(qu, bbu + p * 16 * PITCH);
                bg[2 * p][0] = qg[0]; bg[2 * p][1] = qg[1];
                bg[2 * p + 1][0] = qg[2]; bg[2 * p + 1][1] = qg[3];
                bu[2 * p][0] = qu[0]; bu[2 * p][1] = qu[1];
                bu[2 * p + 1][0] = qu[2]; bu[2 * p + 1][1] = qu[3];
            }
            #pragma unroll
            for (int mt = 0; mt < 2; ++mt)
                #pragma unroll
                for (int nt = 0; nt < 4; ++nt) {
                    mma_bf16(accG[mt][nt], ag[mt], bg[nt]);
                    mma_bf16(accU[mt][nt], au[mt], bu[nt]);
                }
        }
        __syncthreads();
    }

    // swiglu epilogue -> Y bf16
    #pragma unroll
    for (int mt = 0; mt < 2; ++mt) {
        #pragma unroll
        for (int half = 0; half < 2; ++half) {
            int r = wm * 32 + mt * 16 + half * 8 + gq;
            int gi = i0 + r;
            if (gi >= iend) continue;
            size_t rowoff = (size_t)gi * DI + nb;
            #pragma unroll
            for (int nt = 0; nt < 4; ++nt) {
                int cc = wn * 32 + nt * 8 + 2 * tig;
                float g0 = accG[mt][nt][half * 2 + 0];
                float g1 = accG[mt][nt][half * 2 + 1];
                float u0 = accU[mt][nt][half * 2 + 0];
                float u1 = accU[mt][nt][half * 2 + 1];
                float y0 = u0 * g0 / (1.f + __expf(-g0));
                float y1 = u1 * g1 / (1.f + __expf(-g1));
                __nv_bfloat162 o = __floats2bfloat162_rn(y0, y1);
                *(uint32_t*)&Y[rowoff + cc] = *(uint32_t*)&o;
            }
        }
    }
}

// ===================== split-K reduce -> bf16 ================================
template<int S>
__global__ void reduce_bf(const float4* __restrict__ P, uint2* __restrict__ O,
                          int n4, size_t stride4)
{
    int i = blockIdx.x * 256 + threadIdx.x;
    if (i >= n4) return;
    float4 s = P[i];
    #pragma unroll
    for (int k = 1; k < S; ++k) {
        float4 v = P[(size_t)k * stride4 + i];
        s.x += v.x; s.y += v.y; s.z += v.z; s.w += v.w;
    }
    __nv_bfloat162 lo = __floats2bfloat162_rn(s.x, s.y);
    __nv_bfloat162 hi = __floats2bfloat162_rn(s.z, s.w);
    uint2 o; o.x = *(uint32_t*)&lo; o.y = *(uint32_t*)&hi;
    O[i] = o;
}

// ===================== launch ================================================
extern "C" void kernel_launch(void* const* d_in, const int* in_sizes, int n_in,
                              void* d_out, int out_size)
{
    const float* x         = (const float*)d_in[0];
    const int*   eidx      = (const int*)  d_in[1];
    const float* gate_A    = (const float*)d_in[2];
    const float* gate_C    = (const float*)d_in[3];
    const float* gate_B    = (const float*)d_in[4];
    const float* up_A      = (const float*)d_in[5];
    const float* up_C      = (const float*)d_in[6];
    const float* up_B      = (const float*)d_in[7];
    const float* down_A    = (const float*)d_in[8];
    const float* down_C    = (const float*)d_in[9];
    const float* down_B    = (const float*)d_in[10];
    const float* down_bias = (const float*)d_in[11];
    float* out = (float*)d_out;

    __nv_bfloat16 *pXb, *pW1, *pAd, *pBg, *pBu, *pBd, *pW2, *pCd,
                  *pH, *pH2, *pY, *pHd, *pHd2;
    float *pP1, *pP3;
    cudaGetSymbolAddress((void**)&pXb,  g_Xb);
    cudaGetSymbolAddress((void**)&pW1,  g_W1);
    cudaGetSymbolAddress((void**)&pAd,  g_Ad);
    cudaGetSymbolAddress((void**)&pBg,  g_Bg);
    cudaGetSymbolAddress((void**)&pBu,  g_Bu);
    cudaGetSymbolAddress((void**)&pBd,  g_Bd);
    cudaGetSymbolAddress((void**)&pW2,  g_W2);
    cudaGetSymbolAddress((void**)&pCd,  g_Cd);
    cudaGetSymbolAddress((void**)&pH,   g_H);
    cudaGetSymbolAddress((void**)&pH2,  g_H2);
    cudaGetSymbolAddress((void**)&pY,   g_Y);
    cudaGetSymbolAddress((void**)&pHd,  g_Hd);
    cudaGetSymbolAddress((void**)&pHd2, g_Hd2);
    cudaGetSymbolAddress((void**)&pP1,  g_P1);
    cudaGetSymbolAddress((void**)&pP3,  g_P3);

    const int SM1 = 4 * ABUF + 1024;               // 41984
    const int SM2 = 4 * ABUF + 4 * BBUF2 + 512;    // 61952
    cudaFuncSetAttribute(mma1<true,  false, 0, 4>, cudaFuncAttributeMaxDynamicSharedMemorySize, SM1);
    cudaFuncSetAttribute(mma1<false, true,  3, 1>, cudaFuncAttributeMaxDynamicSharedMemorySize, SM1);
    cudaFuncSetAttribute(mma1<false, false, 0, 8>, cudaFuncAttributeMaxDynamicSharedMemorySize, SM1);
    cudaFuncSetAttribute(mma1<false, false, 2, 1>, cudaFuncAttributeMaxDynamicSharedMemorySize, SM1);
    cudaFuncSetAttribute(mma2, cudaFuncAttributeMaxDynamicSharedMemorySize, SM2);

    // permutation
    k_init<<<1, 32>>>();
    k_hist<<<NT / 256, 256>>>(eidx);
    k_scan<<<1, 1>>>();
    k_scatter<<<NT / 256, 256>>>(eidx);

    // conversions
    f2bf<<<(NT * DH / 4 + 255) / 256, 256>>>((const float4*)x, (uint2*)pXb, NT * DH / 4);
    f2bf_pack<<<(NE * 128 * DH / 4 + 255) / 256, 256>>>(
        (const float4*)gate_A, pW1, 128 * DH / 4, (size_t)256 * DH, 0);
    f2bf_pack<<<(NE * 128 * DH / 4 + 255) / 256, 256>>>(
        (const float4*)up_A, pW1, 128 * DH / 4, (size_t)256 * DH, (size_t)128 * DH);
    f2bf<<<(NE * NR * DI / 4 + 255) / 256, 256>>>((const float4*)down_A, (uint2*)pAd, NE * NR * DI / 4);
    f2bf<<<(NE * DI * NR / 4 + 255) / 256, 256>>>((const float4*)gate_B, (uint2*)pBg, NE * DI * NR / 4);
    f2bf<<<(NE * DI * NR / 4 + 255) / 256, 256>>>((const float4*)up_B,   (uint2*)pBu, NE * DI * NR / 4);
    f2bf<<<(NE * DH * NR / 4 + 255) / 256, 256>>>((const float4*)down_B, (uint2*)pBd, NE * DH * NR / 4);
    build_W2<<<(256 * 256 + 255) / 256, 256>>>(gate_C, up_C, pW2);
    f2bf<<<(NR * NR / 4 + 255) / 256, 256>>>((const float4*)down_C, (uint2*)pCd, NR * NR / 4);

    // K1: H = x_perm @ [gate_A; up_A]^T   (split-K 4)
    mma1<true, false, 0, 4><<<dim3(2, NT / 128, NE * 4), 256, SM1>>>(
        pXb, DH, 0, 0, pW1, DH, (size_t)256 * DH, DH,
        pP1, 256, (size_t)NT * 256, nullptr);
    reduce_bf<4><<<(NT * 256 / 4 + 255) / 256, 256>>>(
        (const float4*)pP1, (uint2*)pH, NT * 256 / 4, (size_t)NT * 256 / 4);

    // K1.5: H2 = H @ W2^T  (block-diag C)
    mma1<false, true, 3, 1><<<dim3(2, NT / 128, 1), 256, SM1>>>(
        pH, 256, 0, NT, pW2, 256, 0, 256,
        pH2, 256, 0, nullptr);

    // K2: Y = silu(H2g @ gate_B^T) * (H2u @ up_B^T)
    mma2<<<dim3(DI / 64, NT / 128, NE), 256, SM2>>>(pH2, pBg, pBu, pY);

    // K3: Hd = Y @ down_A^T   (split-K 8)
    mma1<false, false, 0, 8><<<dim3(1, NT / 128, NE * 8), 256, SM1>>>(
        pY, DI, 0, 0, pAd, DI, (size_t)NR * DI, DI,
        pP3, NR, (size_t)NT * NR, nullptr);
    reduce_bf<8><<<(NT * NR / 4 + 255) / 256, 256>>>(
        (const float4*)pP3, (uint2*)pHd, NT * NR / 4, (size_t)NT * NR / 4);

    // K3.5: Hd2 = Hd @ down_C^T
    mma1<false, true, 3, 1><<<dim3(1, NT / 128, 1), 256, SM1>>>(
        pHd, NR, 0, NT, pCd, NR, 0, NR,
        pHd2, NR, 0, nullptr);

    // K4: out[perm[i],:] = Hd2 @ down_B^T + bias[e]
    mma1<false, false, 2, 1><<<dim3(DH / 128, NT / 128, NE), 256, SM1>>>(
        pHd2, NR, 0, 0, pBd, NR, (size_t)DH * NR, NR,
        out, DH, 0, down_bias);
}